// round 10
// baseline (speedup 1.0000x reference)
#include <cuda_runtime.h>
#include <cuda_fp16.h>
#include <cstdint>

#define NB 32
#define NC 512
#define NT 1024
#define SCALE_F 0.04419417382415922f  // 1/sqrt(512)
#define QMAX 16256.0f                 // 127*128
#define INV_QMAX 6.151574803149606e-05f

#define TROW 144                       // 128 int8 (128B) + 16B pad
#define TSZ  (128 * TROW)              // 18432 B per tile (128 rows x k128 int8)
#define SMEM_TILES (2 * 4 * TSZ)       // 2 stages x 4 tiles = 147456
#define SMEM_DYN (SMEM_TILES + 1024)   // + per-tile row/col scale arrays
#define SPAD 132                       // fp32 staging row pad (16B-aligned rows)

// ---------------------------------------------------------------------------
// Scratch (__device__ globals: allocation-free rule)
// ---------------------------------------------------------------------------
// fp16 split intermediates (exact to ~2^-22) for q/k/vT before quantization
__device__ __align__(256) __half g_qhi [(size_t)NB * NC * NT];
__device__ __align__(256) __half g_qlo [(size_t)NB * NC * NT];
__device__ __align__(256) __half g_khi [(size_t)NB * NC * NT];
__device__ __align__(256) __half g_klo [(size_t)NB * NC * NT];
__device__ __align__(256) __half g_vThi[(size_t)NB * NT * NC];
__device__ __align__(256) __half g_vTlo[(size_t)NB * NT * NC];
// int8 limb planes
__device__ __align__(256) signed char g_x8h[(size_t)NB * NT * NC];
__device__ __align__(256) signed char g_x8l[(size_t)NB * NT * NC];
__device__ __align__(256) signed char g_q8h[(size_t)NB * NC * NT];
__device__ __align__(256) signed char g_q8l[(size_t)NB * NC * NT];
__device__ __align__(256) signed char g_k8h[(size_t)NB * NC * NT];
__device__ __align__(256) signed char g_k8l[(size_t)NB * NC * NT];
__device__ __align__(256) signed char g_v8h[(size_t)NB * NT * NC];
__device__ __align__(256) signed char g_v8l[(size_t)NB * NT * NC];
__device__ __align__(256) signed char g_a8h[(size_t)NB * NC * NC];
__device__ __align__(256) signed char g_a8l[(size_t)NB * NC * NC];
__device__ __align__(256) signed char g_w8h[3 * (size_t)NC * NC];
__device__ __align__(256) signed char g_w8l[3 * (size_t)NC * NC];
// scales (s = rowmax/16256) and rowmax accumulators
__device__ __align__(256) float g_sX [(size_t)NB * NT];
__device__ __align__(256) float g_sW [3 * NC];
__device__ __align__(256) float g_rmQ[(size_t)NB * NC];   // rowmax then s
__device__ __align__(256) float g_rmK[(size_t)NB * NC];
__device__ __align__(256) float g_rmV[(size_t)NB * NT];
__device__ __align__(256) float g_sA [(size_t)NB * NC];
// fp32 energy
__device__ __align__(256) float g_e[(size_t)NB * NC * NC];

// ---------------------------------------------------------------------------
// Baseline-ISA helpers
// ---------------------------------------------------------------------------
__device__ __forceinline__ uint32_t cvta_shared_u32(const void* p) {
    uint32_t a;
    asm("{ .reg .u64 t; cvta.to.shared.u64 t, %1; cvt.u32.u64 %0, t; }" : "=r"(a) : "l"(p));
    return a;
}
__device__ __forceinline__ void cpasync16(uint32_t s, const void* g) {
    asm volatile("cp.async.cg.shared.global [%0], [%1], 16;" :: "r"(s), "l"(g));
}
#define CP_COMMIT() asm volatile("cp.async.commit_group;")
#define CP_WAIT1()  asm volatile("cp.async.wait_group 1;")
#define CP_WAIT0()  asm volatile("cp.async.wait_group 0;")

__device__ __forceinline__ void ldm_x4(uint32_t* r, uint32_t addr) {
    asm volatile("ldmatrix.sync.aligned.m8n8.x4.shared.b16 {%0,%1,%2,%3}, [%4];"
                 : "=r"(r[0]), "=r"(r[1]), "=r"(r[2]), "=r"(r[3]) : "r"(addr));
}
// int8 IMMA: m16n8k32, s32 accumulate
__device__ __forceinline__ void mma_s8(int* c, const uint32_t* a, uint32_t b0, uint32_t b1) {
    asm volatile("mma.sync.aligned.m16n8k32.row.col.s32.s8.s8.s32 "
                 "{%0,%1,%2,%3}, {%4,%5,%6,%7}, {%8,%9}, {%0,%1,%2,%3};"
                 : "+r"(c[0]), "+r"(c[1]), "+r"(c[2]), "+r"(c[3])
                 : "r"(a[0]), "r"(a[1]), "r"(a[2]), "r"(a[3]), "r"(b0), "r"(b1));
}

__device__ __forceinline__ uint32_t pack_h2(__half a, __half b) {
    __half2 t = __halves2half2(a, b);
    return *reinterpret_cast<uint32_t*>(&t);
}
__device__ __forceinline__ void split2h(float v, __half& h, __half& l) {
    h = __float2half(v);
    l = __float2half(v - __half2float(h));
}
// quantize 4 floats -> packed h-bytes (ret) and l-bytes (out)
__device__ __forceinline__ uint32_t quant_pack4(const float* v, float invs, uint32_t& lpack) {
    int h[4], l[4];
#pragma unroll
    for (int i = 0; i < 4; i++) {
        float q = v[i] * invs;
        h[i] = __float2int_rn(q * 0.0078125f);
        h[i] = max(-127, min(127, h[i]));
        l[i] = __float2int_rn(q - 128.f * (float)h[i]);
        l[i] = max(-127, min(127, l[i]));
    }
    lpack = (uint32_t)(l[0] & 255) | ((uint32_t)(l[1] & 255) << 8)
          | ((uint32_t)(l[2] & 255) << 16) | ((uint32_t)(l[3] & 255) << 24);
    return (uint32_t)(h[0] & 255) | ((uint32_t)(h[1] & 255) << 8)
         | ((uint32_t)(h[2] & 255) << 16) | ((uint32_t)(h[3] & 255) << 24);
}

// ---------------------------------------------------------------------------
// Prep kernels
// ---------------------------------------------------------------------------
__global__ __launch_bounds__(256) void init_scales(float* a, int na, float* b2, int nb2, float* c, int nc) {
    int i = blockIdx.x * 256 + threadIdx.x;
    if (i < na) a[i] = 0.f;
    if (i < nb2) b2[i] = 0.f;
    if (i < nc) c[i] = 0.f;
}

// column max of x over c for each (b,t) -> s
__global__ __launch_bounds__(256) void colmax_x(const float* __restrict__ x, float* __restrict__ sX) {
    int id = blockIdx.x * 256 + threadIdx.x;   // b*NT + t
    int b = id >> 10, t = id & (NT - 1);
    const float* p = x + (size_t)b * NC * NT + t;
    float m = 0.f;
#pragma unroll 8
    for (int c = 0; c < NC; ++c) m = fmaxf(m, fabsf(p[(size_t)c * NT]));
    sX[id] = fmaxf(m, 1e-30f) * INV_QMAX;
}

// transpose x[b,c,t] -> quantized xT limbs [b,t,c]
__global__ __launch_bounds__(256) void transpose_quant(
    const float* __restrict__ x, const float* __restrict__ sX,
    signed char* __restrict__ xh, signed char* __restrict__ xl)
{
    __shared__ float tile[32][33];
    const int b = blockIdx.z, c0 = blockIdx.y * 32, t0 = blockIdx.x * 32;
    const int tx = threadIdx.x & 31, ty = threadIdx.x >> 5;  // (32, 8)
#pragma unroll
    for (int j = 0; j < 4; ++j)
        tile[ty + j * 8][tx] = x[((size_t)b * NC + c0 + ty + j * 8) * NT + t0 + tx];
    __syncthreads();
    const int tl = threadIdx.x >> 3;         // 0..31 t-local
    const int c4 = (threadIdx.x & 7) * 4;    // quad of c
    int t = t0 + tl;
    float s = sX[(size_t)b * NT + t];
    float invs = 1.0f / s;
    float v[4];
#pragma unroll
    for (int i = 0; i < 4; ++i) v[i] = tile[c4 + i][tl];
    uint32_t lp, hp = quant_pack4(v, invs, lp);
    size_t o = ((size_t)b * NT + t) * NC + c0 + c4;
    *(uint32_t*)(xh + o) = hp;
    *(uint32_t*)(xl + o) = lp;
}

// quantize one W row per block (128 threads, row length 512)
__global__ __launch_bounds__(128) void quantize_w(
    const float* __restrict__ W, signed char* __restrict__ wh, signed char* __restrict__ wl,
    float* __restrict__ sW)
{
    const int d = blockIdx.x, tid = threadIdx.x, lane = tid & 31, warp = tid >> 5;
    __shared__ float smax[4];
    float4 v4 = *(const float4*)&W[(size_t)d * NC + tid * 4];
    float v[4] = {v4.x, v4.y, v4.z, v4.w};
    float m = fmaxf(fmaxf(fabsf(v[0]), fabsf(v[1])), fmaxf(fabsf(v[2]), fabsf(v[3])));
#pragma unroll
    for (int o = 16; o > 0; o >>= 1) m = fmaxf(m, __shfl_xor_sync(0xffffffffu, m, o));
    if (lane == 0) smax[warp] = m;
    __syncthreads();
    m = fmaxf(fmaxf(smax[0], smax[1]), fmaxf(smax[2], smax[3]));
    float s = fmaxf(m, 1e-30f) * INV_QMAX;
    if (tid == 0) sW[d] = s;
    uint32_t lp, hp = quant_pack4(v, 1.0f / s, lp);
    size_t o = (size_t)d * NC + tid * 4;
    *(uint32_t*)(wh + o) = hp;
    *(uint32_t*)(wl + o) = lp;
}

// generic: fp16 hi/lo planes -> int8 limbs using rowmax buffer (then store s back)
__global__ void quantize_rows(
    const __half* __restrict__ hi, const __half* __restrict__ lo,
    signed char* __restrict__ oh, signed char* __restrict__ ol,
    float* __restrict__ rm, int len)
{
    const size_t row = blockIdx.x;
    const int tid = threadIdx.x;
    float rmax = rm[row];
    float s = fmaxf(rmax, 1e-30f) * INV_QMAX;
    float invs = 1.0f / s;
    int q4 = tid;  // quad index
    if (q4 * 4 < len) {
        size_t o = row * (size_t)len + q4 * 4;
        uint2 h2 = *(const uint2*)(hi + o);
        uint2 l2 = *(const uint2*)(lo + o);
        __half2 ha = *reinterpret_cast<__half2*>(&h2.x), hb = *reinterpret_cast<__half2*>(&h2.y);
        __half2 la = *reinterpret_cast<__half2*>(&l2.x), lb = *reinterpret_cast<__half2*>(&l2.y);
        float v[4];
        v[0] = __low2float(ha) + __low2float(la);
        v[1] = __high2float(ha) + __high2float(la);
        v[2] = __low2float(hb) + __low2float(lb);
        v[3] = __high2float(hb) + __high2float(lb);
        uint32_t lp, hp = quant_pack4(v, invs, lp);
        *(uint32_t*)(oh + o) = hp;
        *(uint32_t*)(ol + o) = lp;
    }
    __syncthreads();
    if (tid == 0) rm[row] = s;
}

// ---------------------------------------------------------------------------
// int8 split-2 IMMA GEMM:  D[m,n] = sA[m]*sB[n]*(16384*HH + 128*(HL+LH))
// CTA 128x128, K-chunk 128 int8, 2-stage cp.async, 8 warps (2x4), warp 64x32.
// EPI 0: gate*(D+bias) -> fp16 split planes [b,m,n] + rowmax[m]   (q/k)
// EPI 1: gate*(D+bias) -> transposed fp16 split [b,n,m] + rowmax[n] (v)
// EPI 2: raw fp32 -> fOut
// ---------------------------------------------------------------------------
template <int EPI>
__global__ __launch_bounds__(256, 1) void gemm_i8(
    const signed char* __restrict__ aH, const signed char* __restrict__ aL,
    const signed char* __restrict__ bH, const signed char* __restrict__ bL,
    int aStr, int bStr, size_t aBatch, size_t bBatch, int nCh,
    const float* __restrict__ sa, size_t saB,
    const float* __restrict__ sb, size_t sbB,
    const float* __restrict__ g, const float* __restrict__ bias,
    float* __restrict__ fOut, int oStr, size_t oBatch,
    __half* __restrict__ oHi, __half* __restrict__ oLo,
    float* __restrict__ rmax)
{
    extern __shared__ char sm[];
    const uint32_t smb = cvta_shared_u32(sm);
    const int tid = threadIdx.x, lane = tid & 31, wid = tid >> 5;
    const int wm = wid >> 2, wn = wid & 3;
    const int b = blockIdx.z, mBase = blockIdx.y * 128, nBase = blockIdx.x * 128;

    const signed char* aPH = aH + (size_t)b * aBatch + (size_t)mBase * aStr;
    const signed char* aPL = aL + (size_t)b * aBatch + (size_t)mBase * aStr;
    const signed char* bPH = bH + (size_t)b * bBatch + (size_t)nBase * bStr;
    const signed char* bPL = bL + (size_t)b * bBatch + (size_t)nBase * bStr;

    int acc1[4][4][4];  // hi*hi
    int acc2[4][4][4];  // hi*lo + lo*hi
#pragma unroll
    for (int i = 0; i < 4; i++)
#pragma unroll
        for (int j = 0; j < 4; j++)
#pragma unroll
            for (int p = 0; p < 4; p++) { acc1[i][j][p] = 0; acc2[i][j][p] = 0; }

    const int r8 = tid >> 3, u8 = tid & 7;

    auto load_chunk = [&](int c, int s) {
        const int kk = c * 128;
        const signed char* srcs[4] = { aPH + kk, aPL + kk, bPH + kk, bPL + kk };
        const int strs[4] = { aStr, aStr, bStr, bStr };
#pragma unroll
        for (int t = 0; t < 4; ++t) {
            uint32_t dst = smb + (uint32_t)(s * 4 + t) * TSZ;
            const signed char* sp = srcs[t];
            const int st = strs[t];
#pragma unroll
            for (int it = 0; it < 4; ++it) {
                int r = r8 + it * 32;
                cpasync16(dst + r * TROW + u8 * 16, sp + (size_t)r * st + u8 * 16);
            }
        }
    };

    auto compute_chunk = [&](int s) {
        const uint32_t tA0 = smb + (uint32_t)(s * 4 + 0) * TSZ;  // A hi
        const uint32_t tA1 = smb + (uint32_t)(s * 4 + 1) * TSZ;  // A lo
        const uint32_t tB0 = smb + (uint32_t)(s * 4 + 2) * TSZ;  // B hi
        const uint32_t tB1 = smb + (uint32_t)(s * 4 + 3) * TSZ;  // B lo
        const int aRow = wm * 64 + (lane & 15);
        const int aKo  = (lane >> 4) * 16;
        const int bRow = wn * 32 + (lane & 7) + ((lane >> 4) << 3);
        const int bKo  = ((lane >> 3) & 1) * 16;
#pragma unroll
        for (int ks = 0; ks < 4; ++ks) {   // 4 x k32 = k128
            uint32_t aF[2][4][4];
            uint32_t bF[2][2][4];
#pragma unroll
            for (int mi = 0; mi < 4; ++mi) {
                uint32_t off = (uint32_t)((aRow + mi * 16) * TROW + ks * 32 + aKo);
                ldm_x4(aF[0][mi], tA0 + off);
                ldm_x4(aF[1][mi], tA1 + off);
            }
#pragma unroll
            for (int jj = 0; jj < 2; ++jj) {
                uint32_t off = (uint32_t)((bRow + jj * 16) * TROW + ks * 32 + bKo);
                ldm_x4(bF[0][jj], tB0 + off);
                ldm_x4(bF[1][jj], tB1 + off);
            }
#pragma unroll
            for (int mi = 0; mi < 4; ++mi)
#pragma unroll
                for (int nj = 0; nj < 4; ++nj) {
                    const int jj = nj >> 1, p = (nj & 1) * 2;
                    mma_s8(acc1[mi][nj], aF[0][mi], bF[0][jj][p], bF[0][jj][p + 1]); // hh
                    mma_s8(acc2[mi][nj], aF[0][mi], bF[1][jj][p], bF[1][jj][p + 1]); // hl
                    mma_s8(acc2[mi][nj], aF[1][mi], bF[0][jj][p], bF[0][jj][p + 1]); // lh
                }
        }
    };

    load_chunk(0, 0);
    CP_COMMIT();
    for (int c = 0; c < nCh; ++c) {
        if (c + 1 < nCh) {
            load_chunk(c + 1, (c + 1) & 1);
            CP_COMMIT();
            CP_WAIT1();
        } else {
            CP_WAIT0();
        }
        __syncthreads();
        compute_chunk(c & 1);
        __syncthreads();
    }

    // ---- load row/col scales into dedicated smem region
    float* saS = (float*)(sm + SMEM_TILES);
    float* sbS = saS + 128;
    if (tid < 128) saS[tid] = sa[(size_t)b * saB + mBase + tid];
    else           sbS[tid - 128] = sb[(size_t)b * sbB + nBase + (tid - 128)];
    __syncthreads();

    // ---- stage scaled D to smem: stg[128][SPAD]
    float* stg = (float*)sm;
#pragma unroll
    for (int mi = 0; mi < 4; ++mi)
#pragma unroll
        for (int nj = 0; nj < 4; ++nj) {
            int r0 = wm * 64 + mi * 16 + (lane >> 2);
            int cc = wn * 32 + nj * 8 + (lane & 3) * 2;
            float s00 = saS[r0] * sbS[cc], s01 = saS[r0] * sbS[cc + 1];
            float s10 = saS[r0 + 8] * sbS[cc], s11 = saS[r0 + 8] * sbS[cc + 1];
            stg[r0 * SPAD + cc]           = s00 * (16384.f * (float)acc1[mi][nj][0] + 128.f * (float)acc2[mi][nj][0]);
            stg[r0 * SPAD + cc + 1]       = s01 * (16384.f * (float)acc1[mi][nj][1] + 128.f * (float)acc2[mi][nj][1]);
            stg[(r0 + 8) * SPAD + cc]     = s10 * (16384.f * (float)acc1[mi][nj][2] + 128.f * (float)acc2[mi][nj][2]);
            stg[(r0 + 8) * SPAD + cc + 1] = s11 * (16384.f * (float)acc1[mi][nj][3] + 128.f * (float)acc2[mi][nj][3]);
        }
    __syncthreads();

    if (EPI == 2) {
#pragma unroll
        for (int rr = 0; rr < 16; ++rr) {
            int r = rr * 8 + wid;
            float4 v = *(float4*)&stg[r * SPAD + lane * 4];
            *(float4*)&fOut[(size_t)b * oBatch + (size_t)(mBase + r) * oStr + nBase + lane * 4] = v;
        }
    } else if (EPI == 0) {
#pragma unroll
        for (int rr = 0; rr < 16; ++rr) {
            int r = rr * 8 + wid;
            int d = mBase + r;
            float bb = bias[d];
            float4 g4 = *(const float4*)&g[((size_t)b * NC + d) * NT + nBase + lane * 4];
            float4 s4 = *(float4*)&stg[r * SPAD + lane * 4];
            float v0 = g4.x * (s4.x + bb), v1 = g4.y * (s4.y + bb);
            float v2 = g4.z * (s4.z + bb), v3 = g4.w * (s4.w + bb);
            float lm = fmaxf(fmaxf(fabsf(v0), fabsf(v1)), fmaxf(fabsf(v2), fabsf(v3)));
#pragma unroll
            for (int o = 16; o > 0; o >>= 1) lm = fmaxf(lm, __shfl_xor_sync(0xffffffffu, lm, o));
            if (lane == 0) atomicMax((unsigned int*)&rmax[(size_t)b * NC + d], __float_as_uint(lm));
            __half h0, l0, h1, l1, h2, l2, h3, l3;
            split2h(v0, h0, l0); split2h(v1, h1, l1); split2h(v2, h2, l2); split2h(v3, h3, l3);
            size_t o = ((size_t)b * NC + d) * NT + nBase + lane * 4;
            *(uint2*)(oHi + o) = make_uint2(pack_h2(h0, h1), pack_h2(h2, h3));
            *(uint2*)(oLo + o) = make_uint2(pack_h2(l0, l1), pack_h2(l2, l3));
        }
    } else {
        // EPI 1 (v): pass 1 gate in [d][t]
#pragma unroll
        for (int rr = 0; rr < 16; ++rr) {
            int r = rr * 8 + wid;
            int d = mBase + r;
            float bb = bias[d];
            float4 g4 = *(const float4*)&g[((size_t)b * NC + d) * NT + nBase + lane * 4];
            float4 s4 = *(float4*)&stg[r * SPAD + lane * 4];
            s4.x = g4.x * (s4.x + bb); s4.y = g4.y * (s4.y + bb);
            s4.z = g4.z * (s4.z + bb); s4.w = g4.w * (s4.w + bb);
            *(float4*)&stg[r * SPAD + lane * 4] = s4;
        }
        __syncthreads();
        // pass 2: transposed write vT[b,t,d] + rowmax over t-rows
#pragma unroll
        for (int rr = 0; rr < 16; ++rr) {
            int tr = rr * 8 + wid;
            int t = nBase + tr;
            float v0 = stg[(lane * 4 + 0) * SPAD + tr];
            float v1 = stg[(lane * 4 + 1) * SPAD + tr];
            float v2 = stg[(lane * 4 + 2) * SPAD + tr];
            float v3 = stg[(lane * 4 + 3) * SPAD + tr];
            float lm = fmaxf(fmaxf(fabsf(v0), fabsf(v1)), fmaxf(fabsf(v2), fabsf(v3)));
#pragma unroll
            for (int o = 16; o > 0; o >>= 1) lm = fmaxf(lm, __shfl_xor_sync(0xffffffffu, lm, o));
            if (lane == 0) atomicMax((unsigned int*)&rmax[(size_t)b * NT + t], __float_as_uint(lm));
            __half h0, l0, h1, l1, h2, l2, h3, l3;
            split2h(v0, h0, l0); split2h(v1, h1, l1); split2h(v2, h2, l2); split2h(v3, h3, l3);
            size_t o = ((size_t)b * NT + t) * NC + mBase + lane * 4;
            *(uint2*)(oHi + o) = make_uint2(pack_h2(h0, h1), pack_h2(h2, h3));
            *(uint2*)(oLo + o) = make_uint2(pack_h2(l0, l1), pack_h2(l2, l3));
        }
    }
}

// ---------------------------------------------------------------------------
// Softmax + inline int8 quantization of attn (row = (b,c), 512 cols)
// max prob = 1/sum, so q_i = e_i * 16256 directly; s_row = inv/16256.
// ---------------------------------------------------------------------------
__global__ __launch_bounds__(128) void softmax_quant(
    const float* __restrict__ e,
    signed char* __restrict__ ah, signed char* __restrict__ al,
    float* __restrict__ sA)
{
    const size_t row = blockIdx.x;
    const float* p = e + row * NC;
    const int tid = threadIdx.x, lane = tid & 31, warp = tid >> 5;
    __shared__ float smax[4], ssum[4];

    float4 v = *(const float4*)&p[tid * 4];
    float sx = v.x * SCALE_F, sy = v.y * SCALE_F, sz = v.z * SCALE_F, sw = v.w * SCALE_F;

    float m = fmaxf(fmaxf(sx, sy), fmaxf(sz, sw));
#pragma unroll
    for (int o = 16; o > 0; o >>= 1) m = fmaxf(m, __shfl_xor_sync(0xffffffffu, m, o));
    if (lane == 0) smax[warp] = m;
    __syncthreads();
    m = fmaxf(fmaxf(smax[0], smax[1]), fmaxf(smax[2], smax[3]));

    float e0 = __expf(sx - m), e1 = __expf(sy - m), e2 = __expf(sz - m), e3 = __expf(sw - m);
    float s = e0 + e1 + e2 + e3;
#pragma unroll
    for (int o = 16; o > 0; o >>= 1) s += __shfl_xor_sync(0xffffffffu, s, o);
    if (lane == 0) ssum[warp] = s;
    __syncthreads();
    s = ssum[0] + ssum[1] + ssum[2] + ssum[3];
    float inv = 1.0f / s;

    // quantize: p_i = e_i*inv = s_row*(128h+l), s_row = inv/16256 -> q_i = e_i*16256
    float q[4] = { e0 * QMAX, e1 * QMAX, e2 * QMAX, e3 * QMAX };
    uint32_t lp, hp = quant_pack4(q, 1.0f, lp);
    size_t o = row * NC + tid * 4;
    *(uint32_t*)(ah + o) = hp;
    *(uint32_t*)(al + o) = lp;
    if (tid == 0) sA[row] = inv * INV_QMAX;
}

// ---------------------------------------------------------------------------
extern "C" void kernel_launch(void* const* d_in, const int* in_sizes, int n_in,
                              void* d_out, int out_size)
{
    const float* x  = (const float*)d_in[0];
    const float* gq = (const float*)d_in[1];
    const float* gk = (const float*)d_in[2];
    const float* gv = (const float*)d_in[3];
    const float* Wq = (const float*)d_in[4];
    const float* bq = (const float*)d_in[5];
    const float* Wk = (const float*)d_in[6];
    const float* bk = (const float*)d_in[7];
    const float* Wv = (const float*)d_in[8];
    const float* bv = (const float*)d_in[9];
    float* out = (float*)d_out;

    __half *qhi, *qlo, *khi, *klo, *vThi, *vTlo;
    signed char *x8h, *x8l, *q8h, *q8l, *k8h, *k8l, *v8h, *v8l, *a8h, *a8l, *w8h, *w8l;
    float *sX, *sW, *rmQ, *rmK, *rmV, *sA, *e;
    cudaGetSymbolAddress((void**)&qhi, g_qhi);   cudaGetSymbolAddress((void**)&qlo, g_qlo);
    cudaGetSymbolAddress((void**)&khi, g_khi);   cudaGetSymbolAddress((void**)&klo, g_klo);
    cudaGetSymbolAddress((void**)&vThi, g_vThi); cudaGetSymbolAddress((void**)&vTlo, g_vTlo);
    cudaGetSymbolAddress((void**)&x8h, g_x8h);   cudaGetSymbolAddress((void**)&x8l, g_x8l);
    cudaGetSymbolAddress((void**)&q8h, g_q8h);   cudaGetSymbolAddress((void**)&q8l, g_q8l);
    cudaGetSymbolAddress((void**)&k8h, g_k8h);   cudaGetSymbolAddress((void**)&k8l, g_k8l);
    cudaGetSymbolAddress((void**)&v8h, g_v8h);   cudaGetSymbolAddress((void**)&v8l, g_v8l);
    cudaGetSymbolAddress((void**)&a8h, g_a8h);   cudaGetSymbolAddress((void**)&a8l, g_a8l);
    cudaGetSymbolAddress((void**)&w8h, g_w8h);   cudaGetSymbolAddress((void**)&w8l, g_w8l);
    cudaGetSymbolAddress((void**)&sX, g_sX);     cudaGetSymbolAddress((void**)&sW, g_sW);
    cudaGetSymbolAddress((void**)&rmQ, g_rmQ);   cudaGetSymbolAddress((void**)&rmK, g_rmK);
    cudaGetSymbolAddress((void**)&rmV, g_rmV);   cudaGetSymbolAddress((void**)&sA, g_sA);
    cudaGetSymbolAddress((void**)&e, g_e);

    cudaFuncSetAttribute(gemm_i8<0>, cudaFuncAttributeMaxDynamicSharedMemorySize, SMEM_DYN);
    cudaFuncSetAttribute(gemm_i8<1>, cudaFuncAttributeMaxDynamicSharedMemorySize, SMEM_DYN);
    cudaFuncSetAttribute(gemm_i8<2>, cudaFuncAttributeMaxDynamicSharedMemorySize, SMEM_DYN);

    const int WN = NC * NC;

    // 0) zero rowmax buffers (deterministic per replay)
    init_scales<<<128, 256>>>(rmQ, NB * NC, rmK, NB * NC, rmV, NB * NT);

    // 1) x: col-max then transpose+quantize
    colmax_x<<<NB * NT / 256, 256>>>(x, sX);
    dim3 gT(NT / 32, NC / 32, NB);
    transpose_quant<<<gT, 256>>>(x, sX, x8h, x8l);

    // 2) W quantize (per-row)
    quantize_w<<<NC, 128>>>(Wq, w8h,           w8l,           sW);
    quantize_w<<<NC, 128>>>(Wk, w8h + WN,      w8l + WN,      sW + NC);
    quantize_w<<<NC, 128>>>(Wv, w8h + 2 * WN,  w8l + 2 * WN,  sW + 2 * NC);

    // 3) QKV gated linears: M=d, N=t, K=c (4 chunks of 128)
    dim3 gQKV(NT / 128, NC / 128, NB);
    gemm_i8<0><<<gQKV, 256, SMEM_DYN>>>(w8h, w8l, x8h, x8l,
        NC, NC, 0, (size_t)NT * NC, 4, sW, 0, sX, NT,
        gq, bq, nullptr, 0, 0, qhi, qlo, rmQ);
    gemm_i8<0><<<gQKV, 256, SMEM_DYN>>>(w8h + WN, w8l + WN, x8h, x8l,
        NC, NC, 0, (size_t)NT * NC, 4, sW + NC, 0, sX, NT,
        gk, bk, nullptr, 0, 0, khi, klo, rmK);
    gemm_i8<1><<<gQKV, 256, SMEM_DYN>>>(w8h + 2 * WN, w8l + 2 * WN, x8h, x8l,
        NC, NC, 0, (size_t)NT * NC, 4, sW + 2 * NC, 0, sX, NT,
        gv, bv, nullptr, 0, 0, vThi, vTlo, rmV);

    // 4) quantize q, k (rows b*NC, len NT) and vT (rows b*NT, len NC)
    quantize_rows<<<NB * NC, 256>>>(qhi, qlo, q8h, q8l, rmQ, NT);
    quantize_rows<<<NB * NC, 256>>>(khi, klo, k8h, k8l, rmK, NT);
    quantize_rows<<<NB * NT, 128>>>(vThi, vTlo, v8h, v8l, rmV, NC);

    // 5) energy: M=c, N=d, K=t (8 chunks) -> fp32 e
    dim3 gE(NC / 128, NC / 128, NB);
    gemm_i8<2><<<gE, 256, SMEM_DYN>>>(q8h, q8l, k8h, k8l,
        NT, NT, (size_t)NC * NT, (size_t)NC * NT, 8, rmQ, NC, rmK, NC,
        nullptr, nullptr, e, NC, (size_t)NC * NC, nullptr, nullptr, nullptr);

    // 6) softmax + quantize attn
    softmax_quant<<<NB * NC, 128>>>(e, a8h, a8l, sA);

    // 7) out: M=c, N=t, K=d (4 chunks) -> fp32 out
    dim3 gO(NT / 128, NC / 128, NB);
    gemm_i8<2><<<gO, 256, SMEM_DYN>>>(a8h, a8l, v8h, v8l,
        NC, NC, (size_t)NC * NC, (size_t)NT * NC, 4, sA, NC, rmV, NT,
        nullptr, nullptr, out, NT, (size_t)NC * NT, nullptr, nullptr, nullptr);
}

// round 13
// speedup vs baseline: 3.6783x; 3.6783x over previous
#include <cuda_runtime.h>
#include <cuda_fp16.h>
#include <cstdint>

#define NB 32
#define NC 512
#define NT 1024
#define SCALE_F 0.04419417382415922f  // 1/sqrt(512)

#define TROW 144                       // 64 fp16 (128B) + 16B pad
#define TSZ  (128 * TROW)              // 18432 B per tile
#define SMEM_SPLIT (8 * TSZ)           // 2 stages x 4 tiles = 147456
#define SMEM_UNSPL (4 * TSZ)           // 2 stages x 2 tiles = 73728

// ---------------------------------------------------------------------------
// Scratch (__device__ globals: allocation-free rule)
// ---------------------------------------------------------------------------
__device__ __align__(256) __half g_xThi[(size_t)NB * NT * NC];
__device__ __align__(256) __half g_xTlo[(size_t)NB * NT * NC];
__device__ __align__(256) __half g_qh  [(size_t)NB * NC * NT];
__device__ __align__(256) __half g_kh  [(size_t)NB * NC * NT];
__device__ __align__(256) __half g_vThi[(size_t)NB * NT * NC];
__device__ __align__(256) __half g_vTlo[(size_t)NB * NT * NC];
__device__ __align__(256) __half g_ahi [(size_t)NB * NC * NC];
__device__ __align__(256) __half g_alo [(size_t)NB * NC * NC];
__device__ __align__(256) __half g_Whi [3 * (size_t)NC * NC];
__device__ __align__(256) __half g_Wlo [3 * (size_t)NC * NC];
__device__ __align__(256) float  g_e   [(size_t)NB * NC * NC];

// ---------------------------------------------------------------------------
// Baseline-ISA helpers (cp.async / ldmatrix / mma.sync only)
// ---------------------------------------------------------------------------
__device__ __forceinline__ uint32_t cvta_shared_u32(const void* p) {
    uint32_t a;
    asm("{ .reg .u64 t; cvta.to.shared.u64 t, %1; cvt.u32.u64 %0, t; }" : "=r"(a) : "l"(p));
    return a;
}
__device__ __forceinline__ void cpasync16(uint32_t s, const void* g) {
    asm volatile("cp.async.cg.shared.global [%0], [%1], 16;" :: "r"(s), "l"(g));
}
#define CP_COMMIT() asm volatile("cp.async.commit_group;")
#define CP_WAIT1()  asm volatile("cp.async.wait_group 1;")
#define CP_WAIT0()  asm volatile("cp.async.wait_group 0;")

__device__ __forceinline__ void ldm_x4(uint32_t* r, uint32_t addr) {
    asm volatile("ldmatrix.sync.aligned.m8n8.x4.shared.b16 {%0,%1,%2,%3}, [%4];"
                 : "=r"(r[0]), "=r"(r[1]), "=r"(r[2]), "=r"(r[3]) : "r"(addr));
}
__device__ __forceinline__ void mma_f16(float* c, const uint32_t* a, uint32_t b0, uint32_t b1) {
    asm volatile("mma.sync.aligned.m16n8k16.row.col.f32.f16.f16.f32 "
                 "{%0,%1,%2,%3}, {%4,%5,%6,%7}, {%8,%9}, {%0,%1,%2,%3};"
                 : "+f"(c[0]), "+f"(c[1]), "+f"(c[2]), "+f"(c[3])
                 : "r"(a[0]), "r"(a[1]), "r"(a[2]), "r"(a[3]), "r"(b0), "r"(b1));
}

__device__ __forceinline__ uint32_t pack_h2(__half a, __half b) {
    __half2 t = __halves2half2(a, b);
    return *reinterpret_cast<uint32_t*>(&t);
}
__device__ __forceinline__ void split2h(float v, __half& h, __half& l) {
    h = __float2half(v);
    l = __float2half(v - __half2float(h));
}

// ---------------------------------------------------------------------------
// Prep kernels
// ---------------------------------------------------------------------------
__global__ __launch_bounds__(256) void transpose_split(
    const float* __restrict__ x, __half* __restrict__ xHi, __half* __restrict__ xLo)
{
    __shared__ float tile[32][33];
    const int b = blockIdx.z, c0 = blockIdx.y * 32, t0 = blockIdx.x * 32;
    const int tx = threadIdx.x & 31, ty = threadIdx.x >> 5;  // 256 = (32, 8)
#pragma unroll
    for (int j = 0; j < 4; ++j)
        tile[ty + j * 8][tx] = x[((size_t)b * NC + c0 + ty + j * 8) * NT + t0 + tx];
    __syncthreads();
#pragma unroll
    for (int j = 0; j < 4; ++j) {
        int t = t0 + ty + j * 8, cc = c0 + tx;
        float v = tile[tx][ty + j * 8];
        __half h, l; split2h(v, h, l);
        size_t o = ((size_t)b * NT + t) * NC + cc;
        xHi[o] = h; xLo[o] = l;
    }
}

__global__ __launch_bounds__(256) void split_kernel(
    const float* __restrict__ src, __half* __restrict__ hi, __half* __restrict__ lo)
{
    size_t i = ((size_t)blockIdx.x * 256 + threadIdx.x) * 4;
    float4 v = *(const float4*)&src[i];
    __half h0, l0, h1, l1, h2, l2, h3, l3;
    split2h(v.x, h0, l0); split2h(v.y, h1, l1); split2h(v.z, h2, l2); split2h(v.w, h3, l3);
    *(uint2*)(hi + i) = make_uint2(pack_h2(h0, h1), pack_h2(h2, h3));
    *(uint2*)(lo + i) = make_uint2(pack_h2(l0, l1), pack_h2(l2, l3));
}

// ---------------------------------------------------------------------------
// fp16 tensor-core GEMM, selectively split:  D[m,n] = sum_k A[m,k]*B[n,k]
// SPLIT=1: hi*hi + hi*lo + lo*hi (fp32 acc). SPLIT=0: plain fp16 (1 MMA).
// CTA 128x128, K-chunk 64, 2-stage cp.async, 8 warps (2x4), warp 64x32.
// EPI 0: gate*(D+bias) -> single fp16 plane [b,m,n]       (q/k)
// EPI 1: gate*(D+bias) -> transposed split fp16 [b,n,m]   (v)
// EPI 2: raw fp32 -> fOut
// ---------------------------------------------------------------------------
template <int EPI, int SPLIT>
__global__ __launch_bounds__(256) void gemm_tc(
    const __half* __restrict__ aHi, const __half* __restrict__ aLo,
    const __half* __restrict__ bHi, const __half* __restrict__ bLo,
    int aStr, int bStr, size_t aBatch, size_t bBatch, int nCh,
    const float* __restrict__ g, const float* __restrict__ bias,
    float* __restrict__ fOut, int oStr, size_t oBatch,
    __half* __restrict__ oHi, __half* __restrict__ oLo)
{
    extern __shared__ char sm[];
    const uint32_t smb = cvta_shared_u32(sm);
    const int tid = threadIdx.x, lane = tid & 31, wid = tid >> 5;
    const int wm = wid >> 2, wn = wid & 3;
    const int b = blockIdx.z, mBase = blockIdx.y * 128, nBase = blockIdx.x * 128;

    constexpr int NTL = SPLIT ? 4 : 2;        // tiles per stage
    const __half* aPH = aHi + (size_t)b * aBatch + (size_t)mBase * aStr;
    const __half* aPL = aLo + (size_t)b * aBatch + (size_t)mBase * aStr;
    const __half* bPH = bHi + (size_t)b * bBatch + (size_t)nBase * bStr;
    const __half* bPL = bLo + (size_t)b * bBatch + (size_t)nBase * bStr;

    float acc[4][4][4];
#pragma unroll
    for (int i = 0; i < 4; i++)
#pragma unroll
        for (int j = 0; j < 4; j++)
#pragma unroll
            for (int p = 0; p < 4; p++) acc[i][j][p] = 0.f;

    const int r8 = tid >> 3, u8 = tid & 7;  // loader: 32 rows x 8x16B per pass

    auto load_chunk = [&](int c, int s) {
        const int kk = c * 64;
        const __half* srcs[NTL];
        int strs[NTL];
        if (SPLIT) {
            srcs[0] = aPH + kk; srcs[1] = aPL + kk; srcs[2] = bPH + kk; srcs[3] = bPL + kk;
            strs[0] = aStr; strs[1] = aStr; strs[2] = bStr; strs[3] = bStr;
        } else {
            srcs[0] = aPH + kk; srcs[1] = bPH + kk;
            strs[0] = aStr; strs[1] = bStr;
        }
#pragma unroll
        for (int t = 0; t < NTL; ++t) {
            uint32_t dst = smb + (uint32_t)(s * NTL + t) * TSZ;
            const __half* sp = srcs[t];
            const int st = strs[t];
#pragma unroll
            for (int it = 0; it < 4; ++it) {
                int r = r8 + it * 32;
                cpasync16(dst + r * TROW + u8 * 16, sp + (size_t)r * st + u8 * 8);
            }
        }
    };

    auto compute_chunk = [&](int s) {
        const uint32_t sb  = smb + (uint32_t)(s * NTL) * TSZ;
        const uint32_t tA0 = sb;
        const uint32_t tA1 = sb + TSZ;                       // split only
        const uint32_t tB0 = sb + (SPLIT ? 2 : 1) * TSZ;
        const uint32_t tB1 = sb + 3 * TSZ;                   // split only
        const int aRow = wm * 64 + (lane & 15);
        const int aKo  = (lane >> 4) * 16;
        const int bRow = wn * 32 + (lane & 7) + ((lane >> 4) << 3);
        const int bKo  = ((lane >> 3) & 1) * 16;
#pragma unroll
        for (int ks = 0; ks < 4; ++ks) {
            uint32_t aF[2][4][4];
            uint32_t bF[2][2][4];
#pragma unroll
            for (int mi = 0; mi < 4; ++mi) {
                uint32_t off = (uint32_t)((aRow + mi * 16) * TROW + ks * 32 + aKo);
                ldm_x4(aF[0][mi], tA0 + off);
                if (SPLIT) ldm_x4(aF[1][mi], tA1 + off);
            }
#pragma unroll
            for (int jj = 0; jj < 2; ++jj) {
                uint32_t off = (uint32_t)((bRow + jj * 16) * TROW + ks * 32 + bKo);
                ldm_x4(bF[0][jj], tB0 + off);
                if (SPLIT) ldm_x4(bF[1][jj], tB1 + off);
            }
#pragma unroll
            for (int mi = 0; mi < 4; ++mi)
#pragma unroll
                for (int nj = 0; nj < 4; ++nj) {
                    const int jj = nj >> 1, p = (nj & 1) * 2;
                    mma_f16(acc[mi][nj], aF[0][mi], bF[0][jj][p], bF[0][jj][p + 1]);       // hi*hi
                    if (SPLIT) {
                        mma_f16(acc[mi][nj], aF[0][mi], bF[1][jj][p], bF[1][jj][p + 1]);   // hi*lo
                        mma_f16(acc[mi][nj], aF[1][mi], bF[0][jj][p], bF[0][jj][p + 1]);   // lo*hi
                    }
                }
        }
    };

    load_chunk(0, 0);
    CP_COMMIT();
    for (int c = 0; c < nCh; ++c) {
        if (c + 1 < nCh) {
            load_chunk(c + 1, (c + 1) & 1);
            CP_COMMIT();
            CP_WAIT1();
        } else {
            CP_WAIT0();
        }
        __syncthreads();
        compute_chunk(c & 1);
        __syncthreads();
    }

    // ---- stage accumulators to smem: stg[128][132]  (fits in 4*TSZ)
    float* stg = (float*)sm;
#pragma unroll
    for (int mi = 0; mi < 4; ++mi)
#pragma unroll
        for (int nj = 0; nj < 4; ++nj) {
            int r0 = wm * 64 + mi * 16 + (lane >> 2);
            int cc = wn * 32 + nj * 8 + (lane & 3) * 2;
            stg[r0 * 132 + cc]           = acc[mi][nj][0];
            stg[r0 * 132 + cc + 1]       = acc[mi][nj][1];
            stg[(r0 + 8) * 132 + cc]     = acc[mi][nj][2];
            stg[(r0 + 8) * 132 + cc + 1] = acc[mi][nj][3];
        }
    __syncthreads();

    if (EPI == 2) {
#pragma unroll
        for (int rr = 0; rr < 16; ++rr) {
            int r = rr * 8 + wid;
            float4 v = *(float4*)&stg[r * 132 + lane * 4];
            *(float4*)&fOut[(size_t)b * oBatch + (size_t)(mBase + r) * oStr + nBase + lane * 4] = v;
        }
    } else if (EPI == 0) {
        // q/k: single fp16 plane
#pragma unroll
        for (int rr = 0; rr < 16; ++rr) {
            int r = rr * 8 + wid;
            int d = mBase + r;
            float bb = bias[d];
            float4 g4 = *(const float4*)&g[((size_t)b * NC + d) * NT + nBase + lane * 4];
            float4 s4 = *(float4*)&stg[r * 132 + lane * 4];
            __half h0 = __float2half(g4.x * (s4.x + bb));
            __half h1 = __float2half(g4.y * (s4.y + bb));
            __half h2 = __float2half(g4.z * (s4.z + bb));
            __half h3 = __float2half(g4.w * (s4.w + bb));
            size_t o = ((size_t)b * NC + d) * NT + nBase + lane * 4;
            *(uint2*)(oHi + o) = make_uint2(pack_h2(h0, h1), pack_h2(h2, h3));
        }
    } else {
        // v: pass 1 gate in [d][t]; pass 2 transposed split write vT[b,t,d]
#pragma unroll
        for (int rr = 0; rr < 16; ++rr) {
            int r = rr * 8 + wid;
            int d = mBase + r;
            float bb = bias[d];
            float4 g4 = *(const float4*)&g[((size_t)b * NC + d) * NT + nBase + lane * 4];
            float4 s4 = *(float4*)&stg[r * 132 + lane * 4];
            s4.x = g4.x * (s4.x + bb); s4.y = g4.y * (s4.y + bb);
            s4.z = g4.z * (s4.z + bb); s4.w = g4.w * (s4.w + bb);
            *(float4*)&stg[r * 132 + lane * 4] = s4;
        }
        __syncthreads();
#pragma unroll
        for (int rr = 0; rr < 16; ++rr) {
            int tr = rr * 8 + wid;
            int t = nBase + tr;
            float v0 = stg[(lane * 4 + 0) * 132 + tr];
            float v1 = stg[(lane * 4 + 1) * 132 + tr];
            float v2 = stg[(lane * 4 + 2) * 132 + tr];
            float v3 = stg[(lane * 4 + 3) * 132 + tr];
            __half h0, l0, h1, l1, h2, l2, h3, l3;
            split2h(v0, h0, l0); split2h(v1, h1, l1); split2h(v2, h2, l2); split2h(v3, h3, l3);
            size_t o = ((size_t)b * NT + t) * NC + mBase + lane * 4;
            *(uint2*)(oHi + o) = make_uint2(pack_h2(h0, h1), pack_h2(h2, h3));
            *(uint2*)(oLo + o) = make_uint2(pack_h2(l0, l1), pack_h2(l2, l3));
        }
    }
}

// ---------------------------------------------------------------------------
// Softmax over rows of e, emit split fp16 attn planes
// ---------------------------------------------------------------------------
__global__ __launch_bounds__(128) void softmax_split(
    const float* __restrict__ e, __half* __restrict__ aHi, __half* __restrict__ aLo)
{
    const size_t row = blockIdx.x;
    const float* p = e + row * NC;
    const int tid = threadIdx.x, lane = tid & 31, warp = tid >> 5;
    __shared__ float smax[4], ssum[4];

    float4 v = *(const float4*)&p[tid * 4];
    float sx = v.x * SCALE_F, sy = v.y * SCALE_F, sz = v.z * SCALE_F, sw = v.w * SCALE_F;

    float m = fmaxf(fmaxf(sx, sy), fmaxf(sz, sw));
#pragma unroll
    for (int o = 16; o > 0; o >>= 1) m = fmaxf(m, __shfl_xor_sync(0xffffffffu, m, o));
    if (lane == 0) smax[warp] = m;
    __syncthreads();
    m = fmaxf(fmaxf(smax[0], smax[1]), fmaxf(smax[2], smax[3]));

    float e0 = __expf(sx - m), e1 = __expf(sy - m), e2 = __expf(sz - m), e3 = __expf(sw - m);
    float s = e0 + e1 + e2 + e3;
#pragma unroll
    for (int o = 16; o > 0; o >>= 1) s += __shfl_xor_sync(0xffffffffu, s, o);
    if (lane == 0) ssum[warp] = s;
    __syncthreads();
    s = ssum[0] + ssum[1] + ssum[2] + ssum[3];
    float inv = 1.0f / s;

    float r0 = e0 * inv, r1 = e1 * inv, r2 = e2 * inv, r3 = e3 * inv;
    __half h0, l0, h1, l1, h2, l2, h3, l3;
    split2h(r0, h0, l0); split2h(r1, h1, l1); split2h(r2, h2, l2); split2h(r3, h3, l3);
    size_t o = row * NC + tid * 4;
    *(uint2*)(aHi + o) = make_uint2(pack_h2(h0, h1), pack_h2(h2, h3));
    *(uint2*)(aLo + o) = make_uint2(pack_h2(l0, l1), pack_h2(l2, l3));
}

// ---------------------------------------------------------------------------
extern "C" void kernel_launch(void* const* d_in, const int* in_sizes, int n_in,
                              void* d_out, int out_size)
{
    const float* x  = (const float*)d_in[0];
    const float* gq = (const float*)d_in[1];
    const float* gk = (const float*)d_in[2];
    const float* gv = (const float*)d_in[3];
    const float* Wq = (const float*)d_in[4];
    const float* bq = (const float*)d_in[5];
    const float* Wk = (const float*)d_in[6];
    const float* bk = (const float*)d_in[7];
    const float* Wv = (const float*)d_in[8];
    const float* bv = (const float*)d_in[9];
    float* out = (float*)d_out;

    __half *xThi, *xTlo, *qh, *kh, *vThi, *vTlo, *ahi, *alo, *Whi, *Wlo;
    float* e;
    cudaGetSymbolAddress((void**)&xThi, g_xThi);
    cudaGetSymbolAddress((void**)&xTlo, g_xTlo);
    cudaGetSymbolAddress((void**)&qh,   g_qh);
    cudaGetSymbolAddress((void**)&kh,   g_kh);
    cudaGetSymbolAddress((void**)&vThi, g_vThi);
    cudaGetSymbolAddress((void**)&vTlo, g_vTlo);
    cudaGetSymbolAddress((void**)&ahi,  g_ahi);
    cudaGetSymbolAddress((void**)&alo,  g_alo);
    cudaGetSymbolAddress((void**)&Whi,  g_Whi);
    cudaGetSymbolAddress((void**)&Wlo,  g_Wlo);
    cudaGetSymbolAddress((void**)&e,    g_e);

    cudaFuncSetAttribute(gemm_tc<0, 0>, cudaFuncAttributeMaxDynamicSharedMemorySize, SMEM_UNSPL);
    cudaFuncSetAttribute(gemm_tc<1, 1>, cudaFuncAttributeMaxDynamicSharedMemorySize, SMEM_SPLIT);
    cudaFuncSetAttribute(gemm_tc<2, 0>, cudaFuncAttributeMaxDynamicSharedMemorySize, SMEM_UNSPL);
    cudaFuncSetAttribute(gemm_tc<2, 1>, cudaFuncAttributeMaxDynamicSharedMemorySize, SMEM_SPLIT);

    // Prep: transpose+split x; split the three weight matrices (lo used only by V)
    dim3 gT(NT / 32, NC / 32, NB);
    transpose_split<<<gT, 256>>>(x, xThi, xTlo);
    const int WN = NC * NC;
    split_kernel<<<WN / 1024, 256>>>(Wq, Whi,          Wlo);
    split_kernel<<<WN / 1024, 256>>>(Wk, Whi + WN,     Wlo + WN);
    split_kernel<<<WN / 1024, 256>>>(Wv, Whi + 2 * WN, Wlo + 2 * WN);

    // Q/K gated linears (UNSPLIT fp16): M=d, N=t, K=c (8 chunks)
    dim3 gQKV(NT / 128, NC / 128, NB);
    gemm_tc<0, 0><<<gQKV, 256, SMEM_UNSPL>>>(Whi, nullptr, xThi, nullptr,
        NC, NC, 0, (size_t)NT * NC, 8, gq, bq, nullptr, 0, 0, qh, nullptr);
    gemm_tc<0, 0><<<gQKV, 256, SMEM_UNSPL>>>(Whi + WN, nullptr, xThi, nullptr,
        NC, NC, 0, (size_t)NT * NC, 8, gk, bk, nullptr, 0, 0, kh, nullptr);

    // V gated linear (SPLIT): transposed split output vT[b,t,d]
    gemm_tc<1, 1><<<gQKV, 256, SMEM_SPLIT>>>(Whi + 2 * WN, Wlo + 2 * WN, xThi, xTlo,
        NC, NC, 0, (size_t)NT * NC, 8, gv, bv, nullptr, 0, 0, vThi, vTlo);

    // Energy (UNSPLIT fp16): M=c, N=d, K=t (16 chunks) -> fp32 e
    dim3 gE(NC / 128, NC / 128, NB);
    gemm_tc<2, 0><<<gE, 256, SMEM_UNSPL>>>(qh, nullptr, kh, nullptr,
        NT, NT, (size_t)NC * NT, (size_t)NC * NT, 16,
        nullptr, nullptr, e, NC, (size_t)NC * NC, nullptr, nullptr);

    softmax_split<<<NB * NC, 128>>>(e, ahi, alo);

    // Output (SPLIT): M=c, N=t, K=d (8 chunks) -> fp32 out
    dim3 gO(NT / 128, NC / 128, NB);
    gemm_tc<2, 1><<<gO, 256, SMEM_SPLIT>>>(ahi, alo, vThi, vTlo,
        NC, NC, (size_t)NC * NC, (size_t)NT * NC, 8,
        nullptr, nullptr, out, NT, (size_t)NC * NT, nullptr, nullptr);
}

// round 14
// speedup vs baseline: 5.3457x; 1.4533x over previous
#include <cuda_runtime.h>
#include <cuda_fp16.h>
#include <cstdint>

#define NB 32
#define NC 512
#define NT 1024
#define SCALE_F 0.04419417382415922f  // 1/sqrt(512)

#define TROW 144                       // 64 fp16 (128B) + 16B pad
#define TSZ  (128 * TROW)              // 18432 B per tile
#define SMEM_DYN (4 * TSZ)             // 2 stages x 2 tiles = 73728

// ---------------------------------------------------------------------------
// Scratch (__device__ globals: allocation-free rule)
// ---------------------------------------------------------------------------
__device__ __align__(256) __half g_xT [(size_t)NB * NT * NC];   // x^T fp16 [b,t,c]
__device__ __align__(256) __half g_q  [(size_t)NB * NC * NT];   // q fp16 [b,d,t]
__device__ __align__(256) __half g_k  [(size_t)NB * NC * NT];   // k fp16 [b,d,t]
__device__ __align__(256) __half g_vT [(size_t)NB * NT * NC];   // v^T fp16 [b,t,d]
__device__ __align__(256) __half g_a  [(size_t)NB * NC * NC];   // attn fp16 [b,c,d]
__device__ __align__(256) __half g_W  [3 * (size_t)NC * NC];    // Wq,Wk,Wv fp16
__device__ __align__(256) float  g_e  [(size_t)NB * NC * NC];   // energy fp32

// ---------------------------------------------------------------------------
// Baseline-ISA helpers (cp.async / ldmatrix / mma.sync only)
// ---------------------------------------------------------------------------
__device__ __forceinline__ uint32_t cvta_shared_u32(const void* p) {
    uint32_t a;
    asm("{ .reg .u64 t; cvta.to.shared.u64 t, %1; cvt.u32.u64 %0, t; }" : "=r"(a) : "l"(p));
    return a;
}
__device__ __forceinline__ void cpasync16(uint32_t s, const void* g) {
    asm volatile("cp.async.cg.shared.global [%0], [%1], 16;" :: "r"(s), "l"(g));
}
#define CP_COMMIT() asm volatile("cp.async.commit_group;")
#define CP_WAIT1()  asm volatile("cp.async.wait_group 1;")
#define CP_WAIT0()  asm volatile("cp.async.wait_group 0;")

__device__ __forceinline__ void ldm_x4(uint32_t* r, uint32_t addr) {
    asm volatile("ldmatrix.sync.aligned.m8n8.x4.shared.b16 {%0,%1,%2,%3}, [%4];"
                 : "=r"(r[0]), "=r"(r[1]), "=r"(r[2]), "=r"(r[3]) : "r"(addr));
}
__device__ __forceinline__ void mma_f16(float* c, const uint32_t* a, uint32_t b0, uint32_t b1) {
    asm volatile("mma.sync.aligned.m16n8k16.row.col.f32.f16.f16.f32 "
                 "{%0,%1,%2,%3}, {%4,%5,%6,%7}, {%8,%9}, {%0,%1,%2,%3};"
                 : "+f"(c[0]), "+f"(c[1]), "+f"(c[2]), "+f"(c[3])
                 : "r"(a[0]), "r"(a[1]), "r"(a[2]), "r"(a[3]), "r"(b0), "r"(b1));
}
__device__ __forceinline__ uint32_t pack_h2(__half a, __half b) {
    __half2 t = __halves2half2(a, b);
    return *reinterpret_cast<uint32_t*>(&t);
}

// ---------------------------------------------------------------------------
// Prep kernels
// ---------------------------------------------------------------------------
__global__ __launch_bounds__(256) void transpose_half(
    const float* __restrict__ x, __half* __restrict__ xT)
{
    __shared__ float tile[32][33];
    const int b = blockIdx.z, c0 = blockIdx.y * 32, t0 = blockIdx.x * 32;
    const int tx = threadIdx.x & 31, ty = threadIdx.x >> 5;  // (32, 8)
#pragma unroll
    for (int j = 0; j < 4; ++j)
        tile[ty + j * 8][tx] = x[((size_t)b * NC + c0 + ty + j * 8) * NT + t0 + tx];
    __syncthreads();
#pragma unroll
    for (int j = 0; j < 4; ++j) {
        int t = t0 + ty + j * 8, cc = c0 + tx;
        xT[((size_t)b * NT + t) * NC + cc] = __float2half(tile[tx][ty + j * 8]);
    }
}

__global__ __launch_bounds__(256) void conv_half(
    const float* __restrict__ src, __half* __restrict__ dst)
{
    size_t i = ((size_t)blockIdx.x * 256 + threadIdx.x) * 4;
    float4 v = *(const float4*)&src[i];
    *(uint2*)(dst + i) = make_uint2(
        pack_h2(__float2half(v.x), __float2half(v.y)),
        pack_h2(__float2half(v.z), __float2half(v.w)));
}

// ---------------------------------------------------------------------------
// fp16 tensor-core GEMM:  D[m,n] = sum_k A[m,k]*B[n,k]  (fp32 accum)
// CTA 128x128, K-chunk 64, 2-stage cp.async pipeline, 8 warps (2x4), warp 64x32.
// EPI 0: gate*(D+bias) -> fp16 plane [b,m,n]            (q/k)
// EPI 1: gate*(D+bias) -> transposed fp16 plane [b,n,m] (v)
// EPI 2: raw fp32 -> fOut
// ---------------------------------------------------------------------------
template <int EPI>
__global__ __launch_bounds__(256) void gemm_tc(
    const __half* __restrict__ A, const __half* __restrict__ B,
    int aStr, int bStr, size_t aBatch, size_t bBatch, int nCh,
    const float* __restrict__ g, const float* __restrict__ bias,
    float* __restrict__ fOut, int oStr, size_t oBatch,
    __half* __restrict__ oH)
{
    extern __shared__ char sm[];
    const uint32_t smb = cvta_shared_u32(sm);
    const int tid = threadIdx.x, lane = tid & 31, wid = tid >> 5;
    const int wm = wid >> 2, wn = wid & 3;
    const int b = blockIdx.z, mBase = blockIdx.y * 128, nBase = blockIdx.x * 128;

    const __half* aP = A + (size_t)b * aBatch + (size_t)mBase * aStr;
    const __half* bP = B + (size_t)b * bBatch + (size_t)nBase * bStr;

    float acc[4][4][4];
#pragma unroll
    for (int i = 0; i < 4; i++)
#pragma unroll
        for (int j = 0; j < 4; j++)
#pragma unroll
            for (int p = 0; p < 4; p++) acc[i][j][p] = 0.f;

    const int r8 = tid >> 3, u8 = tid & 7;  // loader: 32 rows x 8x16B per pass

    auto load_chunk = [&](int c, int s) {
        const int kk = c * 64;
        uint32_t dstA = smb + (uint32_t)(s * 2 + 0) * TSZ;
        uint32_t dstB = smb + (uint32_t)(s * 2 + 1) * TSZ;
#pragma unroll
        for (int it = 0; it < 4; ++it) {
            int r = r8 + it * 32;
            cpasync16(dstA + r * TROW + u8 * 16, aP + kk + (size_t)r * aStr + u8 * 8);
        }
#pragma unroll
        for (int it = 0; it < 4; ++it) {
            int r = r8 + it * 32;
            cpasync16(dstB + r * TROW + u8 * 16, bP + kk + (size_t)r * bStr + u8 * 8);
        }
    };

    auto compute_chunk = [&](int s) {
        const uint32_t tA = smb + (uint32_t)(s * 2 + 0) * TSZ;
        const uint32_t tB = smb + (uint32_t)(s * 2 + 1) * TSZ;
        const int aRow = wm * 64 + (lane & 15);
        const int aKo  = (lane >> 4) * 16;
        const int bRow = wn * 32 + (lane & 7) + ((lane >> 4) << 3);
        const int bKo  = ((lane >> 3) & 1) * 16;
#pragma unroll
        for (int ks = 0; ks < 4; ++ks) {
            uint32_t aF[4][4];
            uint32_t bF[2][4];
#pragma unroll
            for (int mi = 0; mi < 4; ++mi)
                ldm_x4(aF[mi], tA + (uint32_t)((aRow + mi * 16) * TROW + ks * 32 + aKo));
#pragma unroll
            for (int jj = 0; jj < 2; ++jj)
                ldm_x4(bF[jj], tB + (uint32_t)((bRow + jj * 16) * TROW + ks * 32 + bKo));
#pragma unroll
            for (int mi = 0; mi < 4; ++mi)
#pragma unroll
                for (int nj = 0; nj < 4; ++nj) {
                    const int jj = nj >> 1, p = (nj & 1) * 2;
                    mma_f16(acc[mi][nj], aF[mi], bF[jj][p], bF[jj][p + 1]);
                }
        }
    };

    load_chunk(0, 0);
    CP_COMMIT();
    for (int c = 0; c < nCh; ++c) {
        if (c + 1 < nCh) {
            load_chunk(c + 1, (c + 1) & 1);
            CP_COMMIT();
            CP_WAIT1();
        } else {
            CP_WAIT0();
        }
        __syncthreads();
        compute_chunk(c & 1);
        __syncthreads();
    }

    // ---- stage accumulators to smem: stg[128][132] (66 KB, fits in 4*TSZ)
    float* stg = (float*)sm;
#pragma unroll
    for (int mi = 0; mi < 4; ++mi)
#pragma unroll
        for (int nj = 0; nj < 4; ++nj) {
            int r0 = wm * 64 + mi * 16 + (lane >> 2);
            int cc = wn * 32 + nj * 8 + (lane & 3) * 2;
            stg[r0 * 132 + cc]           = acc[mi][nj][0];
            stg[r0 * 132 + cc + 1]       = acc[mi][nj][1];
            stg[(r0 + 8) * 132 + cc]     = acc[mi][nj][2];
            stg[(r0 + 8) * 132 + cc + 1] = acc[mi][nj][3];
        }
    __syncthreads();

    if (EPI == 2) {
#pragma unroll
        for (int rr = 0; rr < 16; ++rr) {
            int r = rr * 8 + wid;
            float4 v = *(float4*)&stg[r * 132 + lane * 4];
            *(float4*)&fOut[(size_t)b * oBatch + (size_t)(mBase + r) * oStr + nBase + lane * 4] = v;
        }
    } else if (EPI == 0) {
#pragma unroll
        for (int rr = 0; rr < 16; ++rr) {
            int r = rr * 8 + wid;
            int d = mBase + r;
            float bb = bias[d];
            float4 g4 = *(const float4*)&g[((size_t)b * NC + d) * NT + nBase + lane * 4];
            float4 s4 = *(float4*)&stg[r * 132 + lane * 4];
            __half h0 = __float2half(g4.x * (s4.x + bb));
            __half h1 = __float2half(g4.y * (s4.y + bb));
            __half h2 = __float2half(g4.z * (s4.z + bb));
            __half h3 = __float2half(g4.w * (s4.w + bb));
            size_t o = ((size_t)b * NC + d) * NT + nBase + lane * 4;
            *(uint2*)(oH + o) = make_uint2(pack_h2(h0, h1), pack_h2(h2, h3));
        }
    } else {
        // v: pass 1 gate in [d][t] orientation; pass 2 transposed write vT[b,t,d]
#pragma unroll
        for (int rr = 0; rr < 16; ++rr) {
            int r = rr * 8 + wid;
            int d = mBase + r;
            float bb = bias[d];
            float4 g4 = *(const float4*)&g[((size_t)b * NC + d) * NT + nBase + lane * 4];
            float4 s4 = *(float4*)&stg[r * 132 + lane * 4];
            s4.x = g4.x * (s4.x + bb); s4.y = g4.y * (s4.y + bb);
            s4.z = g4.z * (s4.z + bb); s4.w = g4.w * (s4.w + bb);
            *(float4*)&stg[r * 132 + lane * 4] = s4;
        }
        __syncthreads();
#pragma unroll
        for (int rr = 0; rr < 16; ++rr) {
            int tr = rr * 8 + wid;
            int t = nBase + tr;
            __half h0 = __float2half(stg[(lane * 4 + 0) * 132 + tr]);
            __half h1 = __float2half(stg[(lane * 4 + 1) * 132 + tr]);
            __half h2 = __float2half(stg[(lane * 4 + 2) * 132 + tr]);
            __half h3 = __float2half(stg[(lane * 4 + 3) * 132 + tr]);
            size_t o = ((size_t)b * NT + t) * NC + mBase + lane * 4;
            *(uint2*)(oH + o) = make_uint2(pack_h2(h0, h1), pack_h2(h2, h3));
        }
    }
}

// ---------------------------------------------------------------------------
// Softmax over rows of e -> fp16 attn plane
// ---------------------------------------------------------------------------
__global__ __launch_bounds__(128) void softmax_h(
    const float* __restrict__ e, __half* __restrict__ aH)
{
    const size_t row = blockIdx.x;
    const float* p = e + row * NC;
    const int tid = threadIdx.x, lane = tid & 31, warp = tid >> 5;
    __shared__ float smax[4], ssum[4];

    float4 v = *(const float4*)&p[tid * 4];
    float sx = v.x * SCALE_F, sy = v.y * SCALE_F, sz = v.z * SCALE_F, sw = v.w * SCALE_F;

    float m = fmaxf(fmaxf(sx, sy), fmaxf(sz, sw));
#pragma unroll
    for (int o = 16; o > 0; o >>= 1) m = fmaxf(m, __shfl_xor_sync(0xffffffffu, m, o));
    if (lane == 0) smax[warp] = m;
    __syncthreads();
    m = fmaxf(fmaxf(smax[0], smax[1]), fmaxf(smax[2], smax[3]));

    float e0 = __expf(sx - m), e1 = __expf(sy - m), e2 = __expf(sz - m), e3 = __expf(sw - m);
    float s = e0 + e1 + e2 + e3;
#pragma unroll
    for (int o = 16; o > 0; o >>= 1) s += __shfl_xor_sync(0xffffffffu, s, o);
    if (lane == 0) ssum[warp] = s;
    __syncthreads();
    s = ssum[0] + ssum[1] + ssum[2] + ssum[3];
    float inv = 1.0f / s;

    __half h0 = __float2half(e0 * inv), h1 = __float2half(e1 * inv);
    __half h2 = __float2half(e2 * inv), h3 = __float2half(e3 * inv);
    size_t o = row * NC + tid * 4;
    *(uint2*)(aH + o) = make_uint2(pack_h2(h0, h1), pack_h2(h2, h3));
}

// ---------------------------------------------------------------------------
extern "C" void kernel_launch(void* const* d_in, const int* in_sizes, int n_in,
                              void* d_out, int out_size)
{
    const float* x  = (const float*)d_in[0];
    const float* gq = (const float*)d_in[1];
    const float* gk = (const float*)d_in[2];
    const float* gv = (const float*)d_in[3];
    const float* Wq = (const float*)d_in[4];
    const float* bq = (const float*)d_in[5];
    const float* Wk = (const float*)d_in[6];
    const float* bk = (const float*)d_in[7];
    const float* Wv = (const float*)d_in[8];
    const float* bv = (const float*)d_in[9];
    float* out = (float*)d_out;

    __half *xT, *q, *k, *vT, *a, *W;
    float* e;
    cudaGetSymbolAddress((void**)&xT, g_xT);
    cudaGetSymbolAddress((void**)&q,  g_q);
    cudaGetSymbolAddress((void**)&k,  g_k);
    cudaGetSymbolAddress((void**)&vT, g_vT);
    cudaGetSymbolAddress((void**)&a,  g_a);
    cudaGetSymbolAddress((void**)&W,  g_W);
    cudaGetSymbolAddress((void**)&e,  g_e);

    cudaFuncSetAttribute(gemm_tc<0>, cudaFuncAttributeMaxDynamicSharedMemorySize, SMEM_DYN);
    cudaFuncSetAttribute(gemm_tc<1>, cudaFuncAttributeMaxDynamicSharedMemorySize, SMEM_DYN);
    cudaFuncSetAttribute(gemm_tc<2>, cudaFuncAttributeMaxDynamicSharedMemorySize, SMEM_DYN);

    // Prep: transpose x -> fp16 [b,t,c]; convert weights to fp16
    dim3 gT(NT / 32, NC / 32, NB);
    transpose_half<<<gT, 256>>>(x, xT);
    const int WN = NC * NC;
    conv_half<<<WN / 1024, 256>>>(Wq, W);
    conv_half<<<WN / 1024, 256>>>(Wk, W + WN);
    conv_half<<<WN / 1024, 256>>>(Wv, W + 2 * WN);

    // Q/K/V gated linears: M=d, N=t, K=c (8 chunks)
    dim3 gQKV(NT / 128, NC / 128, NB);
    gemm_tc<0><<<gQKV, 256, SMEM_DYN>>>(W, xT,
        NC, NC, 0, (size_t)NT * NC, 8, gq, bq, nullptr, 0, 0, q);
    gemm_tc<0><<<gQKV, 256, SMEM_DYN>>>(W + WN, xT,
        NC, NC, 0, (size_t)NT * NC, 8, gk, bk, nullptr, 0, 0, k);
    gemm_tc<1><<<gQKV, 256, SMEM_DYN>>>(W + 2 * WN, xT,
        NC, NC, 0, (size_t)NT * NC, 8, gv, bv, nullptr, 0, 0, vT);

    // Energy: M=c, N=d, K=t (16 chunks) -> fp32 e
    dim3 gE(NC / 128, NC / 128, NB);
    gemm_tc<2><<<gE, 256, SMEM_DYN>>>(q, k,
        NT, NT, (size_t)NC * NT, (size_t)NC * NT, 16,
        nullptr, nullptr, e, NC, (size_t)NC * NC, nullptr);

    softmax_h<<<NB * NC, 128>>>(e, a);

    // Output: M=c, N=t, K=d (8 chunks) -> fp32 out
    dim3 gO(NT / 128, NC / 128, NB);
    gemm_tc<2><<<gO, 256, SMEM_DYN>>>(a, vT,
        NC, NC, (size_t)NC * NC, (size_t)NT * NC, 8,
        nullptr, nullptr, out, NT, (size_t)NC * NT, nullptr);
}

// round 15
// speedup vs baseline: 5.7888x; 1.0829x over previous
#include <cuda_runtime.h>
#include <cuda_fp16.h>
#include <cstdint>

#define NB 32
#define NC 512
#define NT 1024
#define SCALE_F 0.04419417382415922f  // 1/sqrt(512)

#define TROW 144                       // 64 fp16 (128B) + 16B pad
#define TSZ  (128 * TROW)              // 18432 B per tile
#define SMEM_DYN (4 * TSZ)             // 2 stages x 2 tiles = 73728

// ---------------------------------------------------------------------------
// Scratch (__device__ globals: allocation-free rule)
// ---------------------------------------------------------------------------
__device__ __align__(256) __half g_xT [(size_t)NB * NT * NC];   // x^T fp16 [b,t,c]
__device__ __align__(256) __half g_q  [(size_t)NB * NC * NT];   // q fp16 [b,d,t]
__device__ __align__(256) __half g_k  [(size_t)NB * NC * NT];   // k fp16 [b,d,t]
__device__ __align__(256) __half g_vT [(size_t)NB * NT * NC];   // v^T fp16 [b,t,d]
__device__ __align__(256) __half g_a  [(size_t)NB * NC * NC];   // attn fp16 [b,c,d]
__device__ __align__(256) __half g_W  [3 * (size_t)NC * NC];    // Wq,Wk,Wv fp16
__device__ __align__(256) float  g_e  [(size_t)NB * NC * NC];   // energy fp32

// ---------------------------------------------------------------------------
// Baseline-ISA helpers (cp.async / ldmatrix / mma.sync only)
// ---------------------------------------------------------------------------
__device__ __forceinline__ uint32_t cvta_shared_u32(const void* p) {
    uint32_t a;
    asm("{ .reg .u64 t; cvta.to.shared.u64 t, %1; cvt.u32.u64 %0, t; }" : "=r"(a) : "l"(p));
    return a;
}
__device__ __forceinline__ void cpasync16(uint32_t s, const void* g) {
    asm volatile("cp.async.cg.shared.global [%0], [%1], 16;" :: "r"(s), "l"(g));
}
#define CP_COMMIT() asm volatile("cp.async.commit_group;")
#define CP_WAIT1()  asm volatile("cp.async.wait_group 1;")
#define CP_WAIT0()  asm volatile("cp.async.wait_group 0;")

__device__ __forceinline__ void ldm_x4(uint32_t* r, uint32_t addr) {
    asm volatile("ldmatrix.sync.aligned.m8n8.x4.shared.b16 {%0,%1,%2,%3}, [%4];"
                 : "=r"(r[0]), "=r"(r[1]), "=r"(r[2]), "=r"(r[3]) : "r"(addr));
}
__device__ __forceinline__ void mma_f16(float* c, const uint32_t* a, uint32_t b0, uint32_t b1) {
    asm volatile("mma.sync.aligned.m16n8k16.row.col.f32.f16.f16.f32 "
                 "{%0,%1,%2,%3}, {%4,%5,%6,%7}, {%8,%9}, {%0,%1,%2,%3};"
                 : "+f"(c[0]), "+f"(c[1]), "+f"(c[2]), "+f"(c[3])
                 : "r"(a[0]), "r"(a[1]), "r"(a[2]), "r"(a[3]), "r"(b0), "r"(b1));
}
__device__ __forceinline__ uint32_t pack_h2(__half a, __half b) {
    __half2 t = __halves2half2(a, b);
    return *reinterpret_cast<uint32_t*>(&t);
}

// ---------------------------------------------------------------------------
// Prep kernels
// ---------------------------------------------------------------------------
__global__ __launch_bounds__(256) void transpose_half(
    const float* __restrict__ x, __half* __restrict__ xT)
{
    __shared__ float tile[32][33];
    const int b = blockIdx.z, c0 = blockIdx.y * 32, t0 = blockIdx.x * 32;
    const int tx = threadIdx.x & 31, ty = threadIdx.x >> 5;  // (32, 8)
#pragma unroll
    for (int j = 0; j < 4; ++j)
        tile[ty + j * 8][tx] = x[((size_t)b * NC + c0 + ty + j * 8) * NT + t0 + tx];
    __syncthreads();
#pragma unroll
    for (int j = 0; j < 4; ++j) {
        int t = t0 + ty + j * 8, cc = c0 + tx;
        xT[((size_t)b * NT + t) * NC + cc] = __float2half(tile[tx][ty + j * 8]);
    }
}

// one launch converts all three weight matrices (blockIdx.y selects)
__global__ __launch_bounds__(256) void conv_half3(
    const float* __restrict__ s0, const float* __restrict__ s1,
    const float* __restrict__ s2, __half* __restrict__ dst)
{
    const float* src = (blockIdx.y == 0) ? s0 : (blockIdx.y == 1) ? s1 : s2;
    size_t i = ((size_t)blockIdx.x * 256 + threadIdx.x) * 4;
    float4 v = *(const float4*)&src[i];
    size_t o = (size_t)blockIdx.y * NC * NC + i;
    *(uint2*)(dst + o) = make_uint2(
        pack_h2(__float2half(v.x), __float2half(v.y)),
        pack_h2(__float2half(v.z), __float2half(v.w)));
}

// ---------------------------------------------------------------------------
// Shared GEMM mainloop body (macro-free via inline functions + lambdas)
// CTA 128x128, K-chunk 64, 2-stage cp.async, 8 warps (2x4), warp 64x32.
// ---------------------------------------------------------------------------
struct GemmCore {
    uint32_t smb;
    int lane, wid, wm, wn;
    const __half *aP, *bP;
    int aStr, bStr;
    int r8, u8;
    float acc[4][4][4];

    __device__ __forceinline__ void init(uint32_t smb_, int tid,
                                         const __half* aP_, const __half* bP_,
                                         int aStr_, int bStr_) {
        smb = smb_; lane = tid & 31; wid = tid >> 5;
        wm = wid >> 2; wn = wid & 3;
        aP = aP_; bP = bP_; aStr = aStr_; bStr = bStr_;
        r8 = tid >> 3; u8 = tid & 7;
#pragma unroll
        for (int i = 0; i < 4; i++)
#pragma unroll
            for (int j = 0; j < 4; j++)
#pragma unroll
                for (int p = 0; p < 4; p++) acc[i][j][p] = 0.f;
    }
    __device__ __forceinline__ void load_chunk(int c, int s) {
        const int kk = c * 64;
        uint32_t dstA = smb + (uint32_t)(s * 2 + 0) * TSZ;
        uint32_t dstB = smb + (uint32_t)(s * 2 + 1) * TSZ;
#pragma unroll
        for (int it = 0; it < 4; ++it) {
            int r = r8 + it * 32;
            cpasync16(dstA + r * TROW + u8 * 16, aP + kk + (size_t)r * aStr + u8 * 8);
        }
#pragma unroll
        for (int it = 0; it < 4; ++it) {
            int r = r8 + it * 32;
            cpasync16(dstB + r * TROW + u8 * 16, bP + kk + (size_t)r * bStr + u8 * 8);
        }
    }
    __device__ __forceinline__ void compute_chunk(int s) {
        const uint32_t tA = smb + (uint32_t)(s * 2 + 0) * TSZ;
        const uint32_t tB = smb + (uint32_t)(s * 2 + 1) * TSZ;
        const int aRow = wm * 64 + (lane & 15);
        const int aKo  = (lane >> 4) * 16;
        const int bRow = wn * 32 + (lane & 7) + ((lane >> 4) << 3);
        const int bKo  = ((lane >> 3) & 1) * 16;
#pragma unroll
        for (int ks = 0; ks < 4; ++ks) {
            uint32_t aF[4][4];
            uint32_t bF[2][4];
#pragma unroll
            for (int mi = 0; mi < 4; ++mi)
                ldm_x4(aF[mi], tA + (uint32_t)((aRow + mi * 16) * TROW + ks * 32 + aKo));
#pragma unroll
            for (int jj = 0; jj < 2; ++jj)
                ldm_x4(bF[jj], tB + (uint32_t)((bRow + jj * 16) * TROW + ks * 32 + bKo));
#pragma unroll
            for (int mi = 0; mi < 4; ++mi)
#pragma unroll
                for (int nj = 0; nj < 4; ++nj) {
                    const int jj = nj >> 1, p = (nj & 1) * 2;
                    mma_f16(acc[mi][nj], aF[mi], bF[jj][p], bF[jj][p + 1]);
                }
        }
    }
    __device__ __forceinline__ void run(int nCh) {
        load_chunk(0, 0);
        CP_COMMIT();
        for (int c = 0; c < nCh; ++c) {
            if (c + 1 < nCh) {
                load_chunk(c + 1, (c + 1) & 1);
                CP_COMMIT();
                CP_WAIT1();
            } else {
                CP_WAIT0();
            }
            __syncthreads();
            compute_chunk(c & 1);
            __syncthreads();
        }
    }
    __device__ __forceinline__ void stage(float* stg) {
#pragma unroll
        for (int mi = 0; mi < 4; ++mi)
#pragma unroll
            for (int nj = 0; nj < 4; ++nj) {
                int r0 = wm * 64 + mi * 16 + (lane >> 2);
                int cc = wn * 32 + nj * 8 + (lane & 3) * 2;
                stg[r0 * 132 + cc]           = acc[mi][nj][0];
                stg[r0 * 132 + cc + 1]       = acc[mi][nj][1];
                stg[(r0 + 8) * 132 + cc]     = acc[mi][nj][2];
                stg[(r0 + 8) * 132 + cc + 1] = acc[mi][nj][3];
            }
    }
};

// ---------------------------------------------------------------------------
// Merged Q/K/V gated-linear kernel. blockIdx.y in [0,12): matrix = y>>2,
// mBase = (y&3)*128. Matrix 0/1 (q/k) write [b,d,t]; matrix 2 (v) writes
// transposed vT[b,t,d].
// ---------------------------------------------------------------------------
__global__ __launch_bounds__(256) void qkv_fused(
    const __half* __restrict__ W, const __half* __restrict__ xT,
    const float* __restrict__ gq, const float* __restrict__ gk, const float* __restrict__ gv,
    const float* __restrict__ bq, const float* __restrict__ bk, const float* __restrict__ bv,
    __half* __restrict__ q, __half* __restrict__ k, __half* __restrict__ vT)
{
    extern __shared__ char sm[];
    const int tid = threadIdx.x;
    const int b = blockIdx.z;
    const int mat = blockIdx.y >> 2;
    const int mBase = (blockIdx.y & 3) * 128;
    const int nBase = blockIdx.x * 128;

    const float* g    = (mat == 0) ? gq : (mat == 1) ? gk : gv;
    const float* bias = (mat == 0) ? bq : (mat == 1) ? bk : bv;

    GemmCore core;
    core.init(cvta_shared_u32(sm), tid,
              W + (size_t)mat * NC * NC + (size_t)mBase * NC,
              xT + (size_t)b * NT * NC + (size_t)nBase * NC,
              NC, NC);
    core.run(8);  // K = c = 512

    float* stg = (float*)sm;
    core.stage(stg);
    __syncthreads();

    const int lane = tid & 31, wid = tid >> 5;
    if (mat < 2) {
        __half* oH = (mat == 0) ? q : k;
#pragma unroll
        for (int rr = 0; rr < 16; ++rr) {
            int r = rr * 8 + wid;
            int d = mBase + r;
            float bb = bias[d];
            float4 g4 = *(const float4*)&g[((size_t)b * NC + d) * NT + nBase + lane * 4];
            float4 s4 = *(float4*)&stg[r * 132 + lane * 4];
            __half h0 = __float2half(g4.x * (s4.x + bb));
            __half h1 = __float2half(g4.y * (s4.y + bb));
            __half h2 = __float2half(g4.z * (s4.z + bb));
            __half h3 = __float2half(g4.w * (s4.w + bb));
            size_t o = ((size_t)b * NC + d) * NT + nBase + lane * 4;
            *(uint2*)(oH + o) = make_uint2(pack_h2(h0, h1), pack_h2(h2, h3));
        }
    } else {
        // v: gate in place, then transposed write vT[b,t,d]
#pragma unroll
        for (int rr = 0; rr < 16; ++rr) {
            int r = rr * 8 + wid;
            int d = mBase + r;
            float bb = bias[d];
            float4 g4 = *(const float4*)&g[((size_t)b * NC + d) * NT + nBase + lane * 4];
            float4 s4 = *(float4*)&stg[r * 132 + lane * 4];
            s4.x = g4.x * (s4.x + bb); s4.y = g4.y * (s4.y + bb);
            s4.z = g4.z * (s4.z + bb); s4.w = g4.w * (s4.w + bb);
            *(float4*)&stg[r * 132 + lane * 4] = s4;
        }
        __syncthreads();
#pragma unroll
        for (int rr = 0; rr < 16; ++rr) {
            int tr = rr * 8 + wid;
            int t = nBase + tr;
            __half h0 = __float2half(stg[(lane * 4 + 0) * 132 + tr]);
            __half h1 = __float2half(stg[(lane * 4 + 1) * 132 + tr]);
            __half h2 = __float2half(stg[(lane * 4 + 2) * 132 + tr]);
            __half h3 = __float2half(stg[(lane * 4 + 3) * 132 + tr]);
            size_t o = ((size_t)b * NT + t) * NC + mBase + lane * 4;
            *(uint2*)(vT + o) = make_uint2(pack_h2(h0, h1), pack_h2(h2, h3));
        }
    }
}

// ---------------------------------------------------------------------------
// Generic NT GEMM with raw fp32 output (energy and out stages)
// ---------------------------------------------------------------------------
__global__ __launch_bounds__(256) void gemm_f32out(
    const __half* __restrict__ A, const __half* __restrict__ B,
    int aStr, int bStr, size_t aBatch, size_t bBatch, int nCh,
    float* __restrict__ fOut, int oStr, size_t oBatch)
{
    extern __shared__ char sm[];
    const int tid = threadIdx.x;
    const int b = blockIdx.z, mBase = blockIdx.y * 128, nBase = blockIdx.x * 128;

    GemmCore core;
    core.init(cvta_shared_u32(sm), tid,
              A + (size_t)b * aBatch + (size_t)mBase * aStr,
              B + (size_t)b * bBatch + (size_t)nBase * bStr,
              aStr, bStr);
    core.run(nCh);

    float* stg = (float*)sm;
    core.stage(stg);
    __syncthreads();

    const int lane = tid & 31, wid = tid >> 5;
#pragma unroll
    for (int rr = 0; rr < 16; ++rr) {
        int r = rr * 8 + wid;
        float4 v = *(float4*)&stg[r * 132 + lane * 4];
        *(float4*)&fOut[(size_t)b * oBatch + (size_t)(mBase + r) * oStr + nBase + lane * 4] = v;
    }
}

// ---------------------------------------------------------------------------
// Softmax over rows of e -> fp16 attn plane
// ---------------------------------------------------------------------------
__global__ __launch_bounds__(128) void softmax_h(
    const float* __restrict__ e, __half* __restrict__ aH)
{
    const size_t row = blockIdx.x;
    const float* p = e + row * NC;
    const int tid = threadIdx.x, lane = tid & 31, warp = tid >> 5;
    __shared__ float smax[4], ssum[4];

    float4 v = *(const float4*)&p[tid * 4];
    float sx = v.x * SCALE_F, sy = v.y * SCALE_F, sz = v.z * SCALE_F, sw = v.w * SCALE_F;

    float m = fmaxf(fmaxf(sx, sy), fmaxf(sz, sw));
#pragma unroll
    for (int o = 16; o > 0; o >>= 1) m = fmaxf(m, __shfl_xor_sync(0xffffffffu, m, o));
    if (lane == 0) smax[warp] = m;
    __syncthreads();
    m = fmaxf(fmaxf(smax[0], smax[1]), fmaxf(smax[2], smax[3]));

    float e0 = __expf(sx - m), e1 = __expf(sy - m), e2 = __expf(sz - m), e3 = __expf(sw - m);
    float s = e0 + e1 + e2 + e3;
#pragma unroll
    for (int o = 16; o > 0; o >>= 1) s += __shfl_xor_sync(0xffffffffu, s, o);
    if (lane == 0) ssum[warp] = s;
    __syncthreads();
    s = ssum[0] + ssum[1] + ssum[2] + ssum[3];
    float inv = 1.0f / s;

    __half h0 = __float2half(e0 * inv), h1 = __float2half(e1 * inv);
    __half h2 = __float2half(e2 * inv), h3 = __float2half(e3 * inv);
    size_t o = row * NC + tid * 4;
    *(uint2*)(aH + o) = make_uint2(pack_h2(h0, h1), pack_h2(h2, h3));
}

// ---------------------------------------------------------------------------
extern "C" void kernel_launch(void* const* d_in, const int* in_sizes, int n_in,
                              void* d_out, int out_size)
{
    const float* x  = (const float*)d_in[0];
    const float* gq = (const float*)d_in[1];
    const float* gk = (const float*)d_in[2];
    const float* gv = (const float*)d_in[3];
    const float* Wq = (const float*)d_in[4];
    const float* bq = (const float*)d_in[5];
    const float* Wk = (const float*)d_in[6];
    const float* bk = (const float*)d_in[7];
    const float* Wv = (const float*)d_in[8];
    const float* bv = (const float*)d_in[9];
    float* out = (float*)d_out;

    __half *xT, *q, *k, *vT, *a, *W;
    float* e;
    cudaGetSymbolAddress((void**)&xT, g_xT);
    cudaGetSymbolAddress((void**)&q,  g_q);
    cudaGetSymbolAddress((void**)&k,  g_k);
    cudaGetSymbolAddress((void**)&vT, g_vT);
    cudaGetSymbolAddress((void**)&a,  g_a);
    cudaGetSymbolAddress((void**)&W,  g_W);
    cudaGetSymbolAddress((void**)&e,  g_e);

    cudaFuncSetAttribute(qkv_fused,  cudaFuncAttributeMaxDynamicSharedMemorySize, SMEM_DYN);
    cudaFuncSetAttribute(gemm_f32out, cudaFuncAttributeMaxDynamicSharedMemorySize, SMEM_DYN);

    // Prep: transpose x -> fp16 [b,t,c]; convert all three weights in one launch
    dim3 gT(NT / 32, NC / 32, NB);
    transpose_half<<<gT, 256>>>(x, xT);
    conv_half3<<<dim3(NC * NC / 1024, 3), 256>>>(Wq, Wk, Wv, W);

    // Fused Q/K/V gated linears: grid (8 t-tiles, 12 = 3 matrices x 4 d-tiles, 32 b)
    dim3 gQKV(NT / 128, 12, NB);
    qkv_fused<<<gQKV, 256, SMEM_DYN>>>(W, xT, gq, gk, gv, bq, bk, bv, q, k, vT);

    // Energy: M=c, N=d, K=t (16 chunks) -> fp32 e
    dim3 gE(NC / 128, NC / 128, NB);
    gemm_f32out<<<gE, 256, SMEM_DYN>>>(q, k,
        NT, NT, (size_t)NC * NT, (size_t)NC * NT, 16,
        e, NC, (size_t)NC * NC);

    softmax_h<<<NB * NC, 128>>>(e, a);

    // Output: M=c, N=t, K=d (8 chunks) -> fp32 out
    dim3 gO(NT / 128, NC / 128, NB);
    gemm_f32out<<<gO, 256, SMEM_DYN>>>(a, vT,
        NC, NC, (size_t)NC * NC, (size_t)NT * NC, 8,
        out, NT, (size_t)NC * NT);
}

// round 16
// speedup vs baseline: 5.8176x; 1.0050x over previous
#include <cuda_runtime.h>
#include <cuda_fp16.h>
#include <cstdint>

#define NB 32
#define NC 512
#define NT 1024
#define SCALE_F 0.04419417382415922f  // 1/sqrt(512)

#define TROW 144                       // 64 fp16 (128B) + 16B pad
#define TSZ  (128 * TROW)              // 18432 B per tile
#define SMEM_DYN (4 * TSZ)             // 2 stages x 2 tiles = 73728

// ---------------------------------------------------------------------------
// Scratch (__device__ globals: allocation-free rule)
// ---------------------------------------------------------------------------
__device__ __align__(256) __half g_xT [(size_t)NB * NT * NC];   // x^T fp16 [b,t,c]
__device__ __align__(256) __half g_q  [(size_t)NB * NC * NT];   // q fp16 [b,d,t]
__device__ __align__(256) __half g_k  [(size_t)NB * NC * NT];   // k fp16 [b,d,t]
__device__ __align__(256) __half g_vT [(size_t)NB * NT * NC];   // v^T fp16 [b,t,d]
__device__ __align__(256) __half g_a  [(size_t)NB * NC * NC];   // attn fp16 [b,c,d]
__device__ __align__(256) __half g_W  [3 * (size_t)NC * NC];    // Wq,Wk,Wv fp16
__device__ __align__(256) float  g_e  [(size_t)NB * NC * NC];   // energy fp32

// ---------------------------------------------------------------------------
// Baseline-ISA helpers (cp.async / ldmatrix / mma.sync only)
// ---------------------------------------------------------------------------
__device__ __forceinline__ uint32_t cvta_shared_u32(const void* p) {
    uint32_t a;
    asm("{ .reg .u64 t; cvta.to.shared.u64 t, %1; cvt.u32.u64 %0, t; }" : "=r"(a) : "l"(p));
    return a;
}
__device__ __forceinline__ void cpasync16(uint32_t s, const void* g) {
    asm volatile("cp.async.cg.shared.global [%0], [%1], 16;" :: "r"(s), "l"(g));
}
#define CP_COMMIT() asm volatile("cp.async.commit_group;")
#define CP_WAIT1()  asm volatile("cp.async.wait_group 1;")
#define CP_WAIT0()  asm volatile("cp.async.wait_group 0;")

__device__ __forceinline__ void ldm_x4(uint32_t* r, uint32_t addr) {
    asm volatile("ldmatrix.sync.aligned.m8n8.x4.shared.b16 {%0,%1,%2,%3}, [%4];"
                 : "=r"(r[0]), "=r"(r[1]), "=r"(r[2]), "=r"(r[3]) : "r"(addr));
}
__device__ __forceinline__ void mma_f16(float* c, const uint32_t* a, uint32_t b0, uint32_t b1) {
    asm volatile("mma.sync.aligned.m16n8k16.row.col.f32.f16.f16.f32 "
                 "{%0,%1,%2,%3}, {%4,%5,%6,%7}, {%8,%9}, {%0,%1,%2,%3};"
                 : "+f"(c[0]), "+f"(c[1]), "+f"(c[2]), "+f"(c[3])
                 : "r"(a[0]), "r"(a[1]), "r"(a[2]), "r"(a[3]), "r"(b0), "r"(b1));
}
__device__ __forceinline__ uint32_t pack_h2(__half a, __half b) {
    __half2 t = __halves2half2(a, b);
    return *reinterpret_cast<uint32_t*>(&t);
}

// ---------------------------------------------------------------------------
// Fused prep: blockIdx.z in [0, NB] — z < NB: transpose batch z of x;
// z == NB: convert all three weight matrices (grid-stride over W).
// ---------------------------------------------------------------------------
__global__ __launch_bounds__(256) void prep_fused(
    const float* __restrict__ x, __half* __restrict__ xT,
    const float* __restrict__ Wq, const float* __restrict__ Wk,
    const float* __restrict__ Wv, __half* __restrict__ W)
{
    if (blockIdx.z < NB) {
        __shared__ float tile[32][33];
        const int b = blockIdx.z, c0 = blockIdx.y * 32, t0 = blockIdx.x * 32;
        const int tx = threadIdx.x & 31, ty = threadIdx.x >> 5;  // (32, 8)
#pragma unroll
        for (int j = 0; j < 4; ++j)
            tile[ty + j * 8][tx] = x[((size_t)b * NC + c0 + ty + j * 8) * NT + t0 + tx];
        __syncthreads();
#pragma unroll
        for (int j = 0; j < 4; ++j) {
            int t = t0 + ty + j * 8, cc = c0 + tx;
            xT[((size_t)b * NT + t) * NC + cc] = __float2half(tile[tx][ty + j * 8]);
        }
    } else {
        // weight conversion: 3 * NC*NC elems = 786432 -> 196608 float4s,
        // grid-stride over the (gridDim.x * gridDim.y) blocks of this z-slice.
        const int WN = NC * NC;
        const int nBlk = gridDim.x * gridDim.y;
        const int blk = blockIdx.y * gridDim.x + blockIdx.x;
        const int nQuads = 3 * WN / 4;
        for (int qd = blk * 256 + threadIdx.x; qd < nQuads; qd += nBlk * 256) {
            size_t i = (size_t)qd * 4;
            const float* src = (i < (size_t)WN) ? Wq : (i < (size_t)(2 * WN)) ? Wk : Wv;
            size_t off = i % WN;
            float4 v = *(const float4*)&src[off];
            *(uint2*)(W + i) = make_uint2(
                pack_h2(__float2half(v.x), __float2half(v.y)),
                pack_h2(__float2half(v.z), __float2half(v.w)));
        }
    }
}

// ---------------------------------------------------------------------------
// Shared GEMM mainloop body
// CTA 128x128, K-chunk 64, 2-stage cp.async, 8 warps (2x4), warp 64x32.
// ---------------------------------------------------------------------------
struct GemmCore {
    uint32_t smb;
    int lane, wid, wm, wn;
    const __half *aP, *bP;
    int aStr, bStr;
    int r8, u8;
    float acc[4][4][4];

    __device__ __forceinline__ void init(uint32_t smb_, int tid,
                                         const __half* aP_, const __half* bP_,
                                         int aStr_, int bStr_) {
        smb = smb_; lane = tid & 31; wid = tid >> 5;
        wm = wid >> 2; wn = wid & 3;
        aP = aP_; bP = bP_; aStr = aStr_; bStr = bStr_;
        r8 = tid >> 3; u8 = tid & 7;
#pragma unroll
        for (int i = 0; i < 4; i++)
#pragma unroll
            for (int j = 0; j < 4; j++)
#pragma unroll
                for (int p = 0; p < 4; p++) acc[i][j][p] = 0.f;
    }
    __device__ __forceinline__ void load_chunk(int c, int s) {
        const int kk = c * 64;
        uint32_t dstA = smb + (uint32_t)(s * 2 + 0) * TSZ;
        uint32_t dstB = smb + (uint32_t)(s * 2 + 1) * TSZ;
#pragma unroll
        for (int it = 0; it < 4; ++it) {
            int r = r8 + it * 32;
            cpasync16(dstA + r * TROW + u8 * 16, aP + kk + (size_t)r * aStr + u8 * 8);
        }
#pragma unroll
        for (int it = 0; it < 4; ++it) {
            int r = r8 + it * 32;
            cpasync16(dstB + r * TROW + u8 * 16, bP + kk + (size_t)r * bStr + u8 * 8);
        }
    }
    __device__ __forceinline__ void compute_chunk(int s) {
        const uint32_t tA = smb + (uint32_t)(s * 2 + 0) * TSZ;
        const uint32_t tB = smb + (uint32_t)(s * 2 + 1) * TSZ;
        const int aRow = wm * 64 + (lane & 15);
        const int aKo  = (lane >> 4) * 16;
        const int bRow = wn * 32 + (lane & 7) + ((lane >> 4) << 3);
        const int bKo  = ((lane >> 3) & 1) * 16;
#pragma unroll
        for (int ks = 0; ks < 4; ++ks) {
            uint32_t aF[4][4];
            uint32_t bF[2][4];
#pragma unroll
            for (int mi = 0; mi < 4; ++mi)
                ldm_x4(aF[mi], tA + (uint32_t)((aRow + mi * 16) * TROW + ks * 32 + aKo));
#pragma unroll
            for (int jj = 0; jj < 2; ++jj)
                ldm_x4(bF[jj], tB + (uint32_t)((bRow + jj * 16) * TROW + ks * 32 + bKo));
#pragma unroll
            for (int mi = 0; mi < 4; ++mi)
#pragma unroll
                for (int nj = 0; nj < 4; ++nj) {
                    const int jj = nj >> 1, p = (nj & 1) * 2;
                    mma_f16(acc[mi][nj], aF[mi], bF[jj][p], bF[jj][p + 1]);
                }
        }
    }
    __device__ __forceinline__ void run(int nCh) {
        load_chunk(0, 0);
        CP_COMMIT();
        for (int c = 0; c < nCh; ++c) {
            if (c + 1 < nCh) {
                load_chunk(c + 1, (c + 1) & 1);
                CP_COMMIT();
                CP_WAIT1();
            } else {
                CP_WAIT0();
            }
            __syncthreads();
            compute_chunk(c & 1);
            __syncthreads();
        }
    }
    __device__ __forceinline__ void stage(float* stg) {
#pragma unroll
        for (int mi = 0; mi < 4; ++mi)
#pragma unroll
            for (int nj = 0; nj < 4; ++nj) {
                int r0 = wm * 64 + mi * 16 + (lane >> 2);
                int cc = wn * 32 + nj * 8 + (lane & 3) * 2;
                stg[r0 * 132 + cc]           = acc[mi][nj][0];
                stg[r0 * 132 + cc + 1]       = acc[mi][nj][1];
                stg[(r0 + 8) * 132 + cc]     = acc[mi][nj][2];
                stg[(r0 + 8) * 132 + cc + 1] = acc[mi][nj][3];
            }
    }
};

// ---------------------------------------------------------------------------
// Merged Q/K/V gated-linear kernel. blockIdx.y in [0,12): matrix = y>>2,
// mBase = (y&3)*128. Matrix 0/1 (q/k) write [b,d,t]; matrix 2 (v) writes
// transposed vT[b,t,d].
// ---------------------------------------------------------------------------
__global__ __launch_bounds__(256) void qkv_fused(
    const __half* __restrict__ W, const __half* __restrict__ xT,
    const float* __restrict__ gq, const float* __restrict__ gk, const float* __restrict__ gv,
    const float* __restrict__ bq, const float* __restrict__ bk, const float* __restrict__ bv,
    __half* __restrict__ q, __half* __restrict__ k, __half* __restrict__ vT)
{
    extern __shared__ char sm[];
    const int tid = threadIdx.x;
    const int b = blockIdx.z;
    const int mat = blockIdx.y >> 2;
    const int mBase = (blockIdx.y & 3) * 128;
    const int nBase = blockIdx.x * 128;

    const float* g    = (mat == 0) ? gq : (mat == 1) ? gk : gv;
    const float* bias = (mat == 0) ? bq : (mat == 1) ? bk : bv;

    GemmCore core;
    core.init(cvta_shared_u32(sm), tid,
              W + (size_t)mat * NC * NC + (size_t)mBase * NC,
              xT + (size_t)b * NT * NC + (size_t)nBase * NC,
              NC, NC);
    core.run(8);  // K = c = 512

    float* stg = (float*)sm;
    core.stage(stg);
    __syncthreads();

    const int lane = tid & 31, wid = tid >> 5;
    if (mat < 2) {
        __half* oH = (mat == 0) ? q : k;
#pragma unroll
        for (int rr = 0; rr < 16; ++rr) {
            int r = rr * 8 + wid;
            int d = mBase + r;
            float bb = bias[d];
            float4 g4 = *(const float4*)&g[((size_t)b * NC + d) * NT + nBase + lane * 4];
            float4 s4 = *(float4*)&stg[r * 132 + lane * 4];
            __half h0 = __float2half(g4.x * (s4.x + bb));
            __half h1 = __float2half(g4.y * (s4.y + bb));
            __half h2 = __float2half(g4.z * (s4.z + bb));
            __half h3 = __float2half(g4.w * (s4.w + bb));
            size_t o = ((size_t)b * NC + d) * NT + nBase + lane * 4;
            *(uint2*)(oH + o) = make_uint2(pack_h2(h0, h1), pack_h2(h2, h3));
        }
    } else {
        // v: gate in place, then transposed write vT[b,t,d]
#pragma unroll
        for (int rr = 0; rr < 16; ++rr) {
            int r = rr * 8 + wid;
            int d = mBase + r;
            float bb = bias[d];
            float4 g4 = *(const float4*)&g[((size_t)b * NC + d) * NT + nBase + lane * 4];
            float4 s4 = *(float4*)&stg[r * 132 + lane * 4];
            s4.x = g4.x * (s4.x + bb); s4.y = g4.y * (s4.y + bb);
            s4.z = g4.z * (s4.z + bb); s4.w = g4.w * (s4.w + bb);
            *(float4*)&stg[r * 132 + lane * 4] = s4;
        }
        __syncthreads();
#pragma unroll
        for (int rr = 0; rr < 16; ++rr) {
            int tr = rr * 8 + wid;
            int t = nBase + tr;
            __half h0 = __float2half(stg[(lane * 4 + 0) * 132 + tr]);
            __half h1 = __float2half(stg[(lane * 4 + 1) * 132 + tr]);
            __half h2 = __float2half(stg[(lane * 4 + 2) * 132 + tr]);
            __half h3 = __float2half(stg[(lane * 4 + 3) * 132 + tr]);
            size_t o = ((size_t)b * NT + t) * NC + mBase + lane * 4;
            *(uint2*)(vT + o) = make_uint2(pack_h2(h0, h1), pack_h2(h2, h3));
        }
    }
}

// ---------------------------------------------------------------------------
// Generic NT GEMM with raw fp32 output (energy and out stages)
// ---------------------------------------------------------------------------
__global__ __launch_bounds__(256) void gemm_f32out(
    const __half* __restrict__ A, const __half* __restrict__ B,
    int aStr, int bStr, size_t aBatch, size_t bBatch, int nCh,
    float* __restrict__ fOut, int oStr, size_t oBatch)
{
    extern __shared__ char sm[];
    const int tid = threadIdx.x;
    const int b = blockIdx.z, mBase = blockIdx.y * 128, nBase = blockIdx.x * 128;

    GemmCore core;
    core.init(cvta_shared_u32(sm), tid,
              A + (size_t)b * aBatch + (size_t)mBase * aStr,
              B + (size_t)b * bBatch + (size_t)nBase * bStr,
              aStr, bStr);
    core.run(nCh);

    float* stg = (float*)sm;
    core.stage(stg);
    __syncthreads();

    const int lane = tid & 31, wid = tid >> 5;
#pragma unroll
    for (int rr = 0; rr < 16; ++rr) {
        int r = rr * 8 + wid;
        float4 v = *(float4*)&stg[r * 132 + lane * 4];
        *(float4*)&fOut[(size_t)b * oBatch + (size_t)(mBase + r) * oStr + nBase + lane * 4] = v;
    }
}

// ---------------------------------------------------------------------------
// Softmax: 2 rows per 256-thread block (threads 0-127 row A, 128-255 row B)
// ---------------------------------------------------------------------------
__global__ __launch_bounds__(256) void softmax_h(
    const float* __restrict__ e, __half* __restrict__ aH)
{
    const int grp = threadIdx.x >> 7;            // 0 or 1
    const int tid = threadIdx.x & 127;
    const size_t row = (size_t)blockIdx.x * 2 + grp;
    const float* p = e + row * NC;
    const int lane = tid & 31, warp = tid >> 5;
    __shared__ float smax[2][4], ssum[2][4];

    float4 v = *(const float4*)&p[tid * 4];
    float sx = v.x * SCALE_F, sy = v.y * SCALE_F, sz = v.z * SCALE_F, sw = v.w * SCALE_F;

    float m = fmaxf(fmaxf(sx, sy), fmaxf(sz, sw));
#pragma unroll
    for (int o = 16; o > 0; o >>= 1) m = fmaxf(m, __shfl_xor_sync(0xffffffffu, m, o));
    if (lane == 0) smax[grp][warp] = m;
    __syncthreads();
    m = fmaxf(fmaxf(smax[grp][0], smax[grp][1]), fmaxf(smax[grp][2], smax[grp][3]));

    float e0 = __expf(sx - m), e1 = __expf(sy - m), e2 = __expf(sz - m), e3 = __expf(sw - m);
    float s = e0 + e1 + e2 + e3;
#pragma unroll
    for (int o = 16; o > 0; o >>= 1) s += __shfl_xor_sync(0xffffffffu, s, o);
    if (lane == 0) ssum[grp][warp] = s;
    __syncthreads();
    s = ssum[grp][0] + ssum[grp][1] + ssum[grp][2] + ssum[grp][3];
    float inv = 1.0f / s;

    __half h0 = __float2half(e0 * inv), h1 = __float2half(e1 * inv);
    __half h2 = __float2half(e2 * inv), h3 = __float2half(e3 * inv);
    size_t o = row * NC + tid * 4;
    *(uint2*)(aH + o) = make_uint2(pack_h2(h0, h1), pack_h2(h2, h3));
}

// ---------------------------------------------------------------------------
extern "C" void kernel_launch(void* const* d_in, const int* in_sizes, int n_in,
                              void* d_out, int out_size)
{
    const float* x  = (const float*)d_in[0];
    const float* gq = (const float*)d_in[1];
    const float* gk = (const float*)d_in[2];
    const float* gv = (const float*)d_in[3];
    const float* Wq = (const float*)d_in[4];
    const float* bq = (const float*)d_in[5];
    const float* Wk = (const float*)d_in[6];
    const float* bk = (const float*)d_in[7];
    const float* Wv = (const float*)d_in[8];
    const float* bv = (const float*)d_in[9];
    float* out = (float*)d_out;

    __half *xT, *q, *k, *vT, *a, *W;
    float* e;
    cudaGetSymbolAddress((void**)&xT, g_xT);
    cudaGetSymbolAddress((void**)&q,  g_q);
    cudaGetSymbolAddress((void**)&k,  g_k);
    cudaGetSymbolAddress((void**)&vT, g_vT);
    cudaGetSymbolAddress((void**)&a,  g_a);
    cudaGetSymbolAddress((void**)&W,  g_W);
    cudaGetSymbolAddress((void**)&e,  g_e);

    cudaFuncSetAttribute(qkv_fused,   cudaFuncAttributeMaxDynamicSharedMemorySize, SMEM_DYN);
    cudaFuncSetAttribute(gemm_f32out, cudaFuncAttributeMaxDynamicSharedMemorySize, SMEM_DYN);

    // Fused prep: z<32 -> transpose x; z==32 slice -> convert Wq/Wk/Wv
    dim3 gP(NT / 32, NC / 32, NB + 1);
    prep_fused<<<gP, 256>>>(x, xT, Wq, Wk, Wv, W);

    // Fused Q/K/V gated linears: grid (8 t-tiles, 12 = 3 matrices x 4 d-tiles, 32 b)
    dim3 gQKV(NT / 128, 12, NB);
    qkv_fused<<<gQKV, 256, SMEM_DYN>>>(W, xT, gq, gk, gv, bq, bk, bv, q, k, vT);

    // Energy: M=c, N=d, K=t (16 chunks) -> fp32 e
    dim3 gE(NC / 128, NC / 128, NB);
    gemm_f32out<<<gE, 256, SMEM_DYN>>>(q, k,
        NT, NT, (size_t)NC * NT, (size_t)NC * NT, 16,
        e, NC, (size_t)NC * NC);

    // Softmax: 2 rows per block
    softmax_h<<<NB * NC / 2, 256>>>(e, a);

    // Output: M=c, N=t, K=d (8 chunks) -> fp32 out
    dim3 gO(NT / 128, NC / 128, NB);
    gemm_f32out<<<gO, 256, SMEM_DYN>>>(a, vT,
        NC, NC, (size_t)NC * NC, (size_t)NT * NC, 8,
        out, NT, (size_t)NC * NT);
}

// round 17
// speedup vs baseline: 5.9865x; 1.0290x over previous
#include <cuda_runtime.h>
#include <cuda_fp16.h>
#include <cstdint>

#define NB 32
#define NC 512
#define NT 1024
#define SCALE_F 0.04419417382415922f  // 1/sqrt(512)

#define TROW 144                       // 64 fp16 (128B) + 16B pad
#define TSZ  (128 * TROW)              // 18432 B per tile
#define NSTG 3                         // pipeline stages
#define SMEM_DYN (NSTG * 2 * TSZ)      // 3 stages x 2 tiles = 110592

// ---------------------------------------------------------------------------
// Scratch (__device__ globals: allocation-free rule)
// ---------------------------------------------------------------------------
__device__ __align__(256) __half g_xT [(size_t)NB * NT * NC];   // x^T fp16 [b,t,c]
__device__ __align__(256) __half g_q  [(size_t)NB * NC * NT];   // q fp16 [b,d,t]
__device__ __align__(256) __half g_k  [(size_t)NB * NC * NT];   // k fp16 [b,d,t]
__device__ __align__(256) __half g_vT [(size_t)NB * NT * NC];   // v^T fp16 [b,t,d]
__device__ __align__(256) __half g_a  [(size_t)NB * NC * NC];   // attn fp16 [b,c,d]
__device__ __align__(256) __half g_W  [3 * (size_t)NC * NC];    // Wq,Wk,Wv fp16
__device__ __align__(256) float  g_e  [(size_t)NB * NC * NC];   // energy fp32

// ---------------------------------------------------------------------------
// Baseline-ISA helpers (cp.async / ldmatrix / mma.sync only)
// ---------------------------------------------------------------------------
__device__ __forceinline__ uint32_t cvta_shared_u32(const void* p) {
    uint32_t a;
    asm("{ .reg .u64 t; cvta.to.shared.u64 t, %1; cvt.u32.u64 %0, t; }" : "=r"(a) : "l"(p));
    return a;
}
__device__ __forceinline__ void cpasync16(uint32_t s, const void* g) {
    asm volatile("cp.async.cg.shared.global [%0], [%1], 16;" :: "r"(s), "l"(g));
}
#define CP_COMMIT() asm volatile("cp.async.commit_group;")
#define CP_WAIT1()  asm volatile("cp.async.wait_group 1;")
#define CP_WAIT0()  asm volatile("cp.async.wait_group 0;")

__device__ __forceinline__ void ldm_x4(uint32_t* r, uint32_t addr) {
    asm volatile("ldmatrix.sync.aligned.m8n8.x4.shared.b16 {%0,%1,%2,%3}, [%4];"
                 : "=r"(r[0]), "=r"(r[1]), "=r"(r[2]), "=r"(r[3]) : "r"(addr));
}
__device__ __forceinline__ void mma_f16(float* c, const uint32_t* a, uint32_t b0, uint32_t b1) {
    asm volatile("mma.sync.aligned.m16n8k16.row.col.f32.f16.f16.f32 "
                 "{%0,%1,%2,%3}, {%4,%5,%6,%7}, {%8,%9}, {%0,%1,%2,%3};"
                 : "+f"(c[0]), "+f"(c[1]), "+f"(c[2]), "+f"(c[3])
                 : "r"(a[0]), "r"(a[1]), "r"(a[2]), "r"(a[3]), "r"(b0), "r"(b1));
}
__device__ __forceinline__ uint32_t pack_h2(__half a, __half b) {
    __half2 t = __halves2half2(a, b);
    return *reinterpret_cast<uint32_t*>(&t);
}

// ---------------------------------------------------------------------------
// Fused prep: blockIdx.z in [0, NB] — z < NB: transpose batch z of x;
// z == NB: convert all three weight matrices (grid-stride over W).
// ---------------------------------------------------------------------------
__global__ __launch_bounds__(256) void prep_fused(
    const float* __restrict__ x, __half* __restrict__ xT,
    const float* __restrict__ Wq, const float* __restrict__ Wk,
    const float* __restrict__ Wv, __half* __restrict__ W)
{
    if (blockIdx.z < NB) {
        __shared__ float tile[32][33];
        const int b = blockIdx.z, c0 = blockIdx.y * 32, t0 = blockIdx.x * 32;
        const int tx = threadIdx.x & 31, ty = threadIdx.x >> 5;  // (32, 8)
#pragma unroll
        for (int j = 0; j < 4; ++j)
            tile[ty + j * 8][tx] = x[((size_t)b * NC + c0 + ty + j * 8) * NT + t0 + tx];
        __syncthreads();
#pragma unroll
        for (int j = 0; j < 4; ++j) {
            int t = t0 + ty + j * 8, cc = c0 + tx;
            xT[((size_t)b * NT + t) * NC + cc] = __float2half(tile[tx][ty + j * 8]);
        }
    } else {
        const int WN = NC * NC;
        const int nBlk = gridDim.x * gridDim.y;
        const int blk = blockIdx.y * gridDim.x + blockIdx.x;
        const int nQuads = 3 * WN / 4;
        for (int qd = blk * 256 + threadIdx.x; qd < nQuads; qd += nBlk * 256) {
            size_t i = (size_t)qd * 4;
            const float* src = (i < (size_t)WN) ? Wq : (i < (size_t)(2 * WN)) ? Wk : Wv;
            size_t off = i % WN;
            float4 v = *(const float4*)&src[off];
            *(uint2*)(W + i) = make_uint2(
                pack_h2(__float2half(v.x), __float2half(v.y)),
                pack_h2(__float2half(v.z), __float2half(v.w)));
        }
    }
}

// ---------------------------------------------------------------------------
// Shared GEMM mainloop: CTA 128x128, K-chunk 64, 3-stage cp.async pipeline
// (ONE __syncthreads per chunk), 8 warps (2x4), warp 64x32.
// ---------------------------------------------------------------------------
struct GemmCore {
    uint32_t smb;
    int lane, wid, wm, wn;
    const __half *aP, *bP;
    int aStr, bStr;
    int r8, u8;
    float acc[4][4][4];

    __device__ __forceinline__ void init(uint32_t smb_, int tid,
                                         const __half* aP_, const __half* bP_,
                                         int aStr_, int bStr_) {
        smb = smb_; lane = tid & 31; wid = tid >> 5;
        wm = wid >> 2; wn = wid & 3;
        aP = aP_; bP = bP_; aStr = aStr_; bStr = bStr_;
        r8 = tid >> 3; u8 = tid & 7;
#pragma unroll
        for (int i = 0; i < 4; i++)
#pragma unroll
            for (int j = 0; j < 4; j++)
#pragma unroll
                for (int p = 0; p < 4; p++) acc[i][j][p] = 0.f;
    }
    __device__ __forceinline__ void load_chunk(int c, int s) {
        const int kk = c * 64;
        uint32_t dstA = smb + (uint32_t)(s * 2 + 0) * TSZ;
        uint32_t dstB = smb + (uint32_t)(s * 2 + 1) * TSZ;
#pragma unroll
        for (int it = 0; it < 4; ++it) {
            int r = r8 + it * 32;
            cpasync16(dstA + r * TROW + u8 * 16, aP + kk + (size_t)r * aStr + u8 * 8);
        }
#pragma unroll
        for (int it = 0; it < 4; ++it) {
            int r = r8 + it * 32;
            cpasync16(dstB + r * TROW + u8 * 16, bP + kk + (size_t)r * bStr + u8 * 8);
        }
    }
    __device__ __forceinline__ void compute_chunk(int s) {
        const uint32_t tA = smb + (uint32_t)(s * 2 + 0) * TSZ;
        const uint32_t tB = smb + (uint32_t)(s * 2 + 1) * TSZ;
        const int aRow = wm * 64 + (lane & 15);
        const int aKo  = (lane >> 4) * 16;
        const int bRow = wn * 32 + (lane & 7) + ((lane >> 4) << 3);
        const int bKo  = ((lane >> 3) & 1) * 16;
#pragma unroll
        for (int ks = 0; ks < 4; ++ks) {
            uint32_t aF[4][4];
            uint32_t bF[2][4];
#pragma unroll
            for (int mi = 0; mi < 4; ++mi)
                ldm_x4(aF[mi], tA + (uint32_t)((aRow + mi * 16) * TROW + ks * 32 + aKo));
#pragma unroll
            for (int jj = 0; jj < 2; ++jj)
                ldm_x4(bF[jj], tB + (uint32_t)((bRow + jj * 16) * TROW + ks * 32 + bKo));
#pragma unroll
            for (int mi = 0; mi < 4; ++mi)
#pragma unroll
                for (int nj = 0; nj < 4; ++nj) {
                    const int jj = nj >> 1, p = (nj & 1) * 2;
                    mma_f16(acc[mi][nj], aF[mi], bF[jj][p], bF[jj][p + 1]);
                }
        }
    }
    // 3-stage pipeline, one barrier per chunk.
    // iter c: wait for chunk c -> barrier (also proves all warps done with
    // chunk c-1, so prefetching chunk c+2 into stage (c+2)%3 = (c-1)%3 is safe)
    // -> compute(c%3) -> prefetch chunk c+2.
    __device__ __forceinline__ void run(int nCh) {
        load_chunk(0, 0); CP_COMMIT();
        load_chunk(1, 1); CP_COMMIT();
        for (int c = 0; c < nCh; ++c) {
            if (c >= nCh - 1) { CP_WAIT0(); } else { CP_WAIT1(); }
            __syncthreads();
            compute_chunk(c % NSTG);
            if (c + 2 < nCh) {
                load_chunk(c + 2, (c + 2) % NSTG);
                CP_COMMIT();
            }
        }
        __syncthreads();  // protect smem reuse by epilogue staging
    }
    __device__ __forceinline__ void stage(float* stg) {
#pragma unroll
        for (int mi = 0; mi < 4; ++mi)
#pragma unroll
            for (int nj = 0; nj < 4; ++nj) {
                int r0 = wm * 64 + mi * 16 + (lane >> 2);
                int cc = wn * 32 + nj * 8 + (lane & 3) * 2;
                stg[r0 * 132 + cc]           = acc[mi][nj][0];
                stg[r0 * 132 + cc + 1]       = acc[mi][nj][1];
                stg[(r0 + 8) * 132 + cc]     = acc[mi][nj][2];
                stg[(r0 + 8) * 132 + cc + 1] = acc[mi][nj][3];
            }
    }
};

// ---------------------------------------------------------------------------
// Merged Q/K/V gated-linear kernel. blockIdx.y in [0,12): matrix = y>>2,
// mBase = (y&3)*128. Matrix 0/1 (q/k) write [b,d,t]; matrix 2 (v) writes
// transposed vT[b,t,d].
// ---------------------------------------------------------------------------
__global__ __launch_bounds__(256) void qkv_fused(
    const __half* __restrict__ W, const __half* __restrict__ xT,
    const float* __restrict__ gq, const float* __restrict__ gk, const float* __restrict__ gv,
    const float* __restrict__ bq, const float* __restrict__ bk, const float* __restrict__ bv,
    __half* __restrict__ q, __half* __restrict__ k, __half* __restrict__ vT)
{
    extern __shared__ char sm[];
    const int tid = threadIdx.x;
    const int b = blockIdx.z;
    const int mat = blockIdx.y >> 2;
    const int mBase = (blockIdx.y & 3) * 128;
    const int nBase = blockIdx.x * 128;

    const float* g    = (mat == 0) ? gq : (mat == 1) ? gk : gv;
    const float* bias = (mat == 0) ? bq : (mat == 1) ? bk : bv;

    GemmCore core;
    core.init(cvta_shared_u32(sm), tid,
              W + (size_t)mat * NC * NC + (size_t)mBase * NC,
              xT + (size_t)b * NT * NC + (size_t)nBase * NC,
              NC, NC);
    core.run(8);  // K = c = 512

    float* stg = (float*)sm;
    core.stage(stg);
    __syncthreads();

    const int lane = tid & 31, wid = tid >> 5;
    if (mat < 2) {
        __half* oH = (mat == 0) ? q : k;
#pragma unroll
        for (int rr = 0; rr < 16; ++rr) {
            int r = rr * 8 + wid;
            int d = mBase + r;
            float bb = bias[d];
            float4 g4 = *(const float4*)&g[((size_t)b * NC + d) * NT + nBase + lane * 4];
            float4 s4 = *(float4*)&stg[r * 132 + lane * 4];
            __half h0 = __float2half(g4.x * (s4.x + bb));
            __half h1 = __float2half(g4.y * (s4.y + bb));
            __half h2 = __float2half(g4.z * (s4.z + bb));
            __half h3 = __float2half(g4.w * (s4.w + bb));
            size_t o = ((size_t)b * NC + d) * NT + nBase + lane * 4;
            *(uint2*)(oH + o) = make_uint2(pack_h2(h0, h1), pack_h2(h2, h3));
        }
    } else {
        // v: gate in place, then transposed write vT[b,t,d]
#pragma unroll
        for (int rr = 0; rr < 16; ++rr) {
            int r = rr * 8 + wid;
            int d = mBase + r;
            float bb = bias[d];
            float4 g4 = *(const float4*)&g[((size_t)b * NC + d) * NT + nBase + lane * 4];
            float4 s4 = *(float4*)&stg[r * 132 + lane * 4];
            s4.x = g4.x * (s4.x + bb); s4.y = g4.y * (s4.y + bb);
            s4.z = g4.z * (s4.z + bb); s4.w = g4.w * (s4.w + bb);
            *(float4*)&stg[r * 132 + lane * 4] = s4;
        }
        __syncthreads();
#pragma unroll
        for (int rr = 0; rr < 16; ++rr) {
            int tr = rr * 8 + wid;
            int t = nBase + tr;
            __half h0 = __float2half(stg[(lane * 4 + 0) * 132 + tr]);
            __half h1 = __float2half(stg[(lane * 4 + 1) * 132 + tr]);
            __half h2 = __float2half(stg[(lane * 4 + 2) * 132 + tr]);
            __half h3 = __float2half(stg[(lane * 4 + 3) * 132 + tr]);
            size_t o = ((size_t)b * NT + t) * NC + mBase + lane * 4;
            *(uint2*)(vT + o) = make_uint2(pack_h2(h0, h1), pack_h2(h2, h3));
        }
    }
}

// ---------------------------------------------------------------------------
// Generic NT GEMM with raw fp32 output (energy and out stages)
// ---------------------------------------------------------------------------
__global__ __launch_bounds__(256) void gemm_f32out(
    const __half* __restrict__ A, const __half* __restrict__ B,
    int aStr, int bStr, size_t aBatch, size_t bBatch, int nCh,
    float* __restrict__ fOut, int oStr, size_t oBatch)
{
    extern __shared__ char sm[];
    const int tid = threadIdx.x;
    const int b = blockIdx.z, mBase = blockIdx.y * 128, nBase = blockIdx.x * 128;

    GemmCore core;
    core.init(cvta_shared_u32(sm), tid,
              A + (size_t)b * aBatch + (size_t)mBase * aStr,
              B + (size_t)b * bBatch + (size_t)nBase * bStr,
              aStr, bStr);
    core.run(nCh);

    float* stg = (float*)sm;
    core.stage(stg);
    __syncthreads();

    const int lane = tid & 31, wid = tid >> 5;
#pragma unroll
    for (int rr = 0; rr < 16; ++rr) {
        int r = rr * 8 + wid;
        float4 v = *(float4*)&stg[r * 132 + lane * 4];
        *(float4*)&fOut[(size_t)b * oBatch + (size_t)(mBase + r) * oStr + nBase + lane * 4] = v;
    }
}

// ---------------------------------------------------------------------------
// Softmax: 2 rows per 256-thread block
// ---------------------------------------------------------------------------
__global__ __launch_bounds__(256) void softmax_h(
    const float* __restrict__ e, __half* __restrict__ aH)
{
    const int grp = threadIdx.x >> 7;            // 0 or 1
    const int tid = threadIdx.x & 127;
    const size_t row = (size_t)blockIdx.x * 2 + grp;
    const float* p = e + row * NC;
    const int lane = tid & 31, warp = tid >> 5;
    __shared__ float smax[2][4], ssum[2][4];

    float4 v = *(const float4*)&p[tid * 4];
    float sx = v.x * SCALE_F, sy = v.y * SCALE_F, sz = v.z * SCALE_F, sw = v.w * SCALE_F;

    float m = fmaxf(fmaxf(sx, sy), fmaxf(sz, sw));
#pragma unroll
    for (int o = 16; o > 0; o >>= 1) m = fmaxf(m, __shfl_xor_sync(0xffffffffu, m, o));
    if (lane == 0) smax[grp][warp] = m;
    __syncthreads();
    m = fmaxf(fmaxf(smax[grp][0], smax[grp][1]), fmaxf(smax[grp][2], smax[grp][3]));

    float e0 = __expf(sx - m), e1 = __expf(sy - m), e2 = __expf(sz - m), e3 = __expf(sw - m);
    float s = e0 + e1 + e2 + e3;
#pragma unroll
    for (int o = 16; o > 0; o >>= 1) s += __shfl_xor_sync(0xffffffffu, s, o);
    if (lane == 0) ssum[grp][warp] = s;
    __syncthreads();
    s = ssum[grp][0] + ssum[grp][1] + ssum[grp][2] + ssum[grp][3];
    float inv = 1.0f / s;

    __half h0 = __float2half(e0 * inv), h1 = __float2half(e1 * inv);
    __half h2 = __float2half(e2 * inv), h3 = __float2half(e3 * inv);
    size_t o = row * NC + tid * 4;
    *(uint2*)(aH + o) = make_uint2(pack_h2(h0, h1), pack_h2(h2, h3));
}

// ---------------------------------------------------------------------------
extern "C" void kernel_launch(void* const* d_in, const int* in_sizes, int n_in,
                              void* d_out, int out_size)
{
    const float* x  = (const float*)d_in[0];
    const float* gq = (const float*)d_in[1];
    const float* gk = (const float*)d_in[2];
    const float* gv = (const float*)d_in[3];
    const float* Wq = (const float*)d_in[4];
    const float* bq = (const float*)d_in[5];
    const float* Wk = (const float*)d_in[6];
    const float* bk = (const float*)d_in[7];
    const float* Wv = (const float*)d_in[8];
    const float* bv = (const float*)d_in[9];
    float* out = (float*)d_out;

    __half *xT, *q, *k, *vT, *a, *W;
    float* e;
    cudaGetSymbolAddress((void**)&xT, g_xT);
    cudaGetSymbolAddress((void**)&q,  g_q);
    cudaGetSymbolAddress((void**)&k,  g_k);
    cudaGetSymbolAddress((void**)&vT, g_vT);
    cudaGetSymbolAddress((void**)&a,  g_a);
    cudaGetSymbolAddress((void**)&W,  g_W);
    cudaGetSymbolAddress((void**)&e,  g_e);

    cudaFuncSetAttribute(qkv_fused,   cudaFuncAttributeMaxDynamicSharedMemorySize, SMEM_DYN);
    cudaFuncSetAttribute(gemm_f32out, cudaFuncAttributeMaxDynamicSharedMemorySize, SMEM_DYN);

    // Fused prep: z<32 -> transpose x; z==32 slice -> convert Wq/Wk/Wv
    dim3 gP(NT / 32, NC / 32, NB + 1);
    prep_fused<<<gP, 256>>>(x, xT, Wq, Wk, Wv, W);

    // Fused Q/K/V gated linears: grid (8 t-tiles, 12 = 3 matrices x 4 d-tiles, 32 b)
    dim3 gQKV(NT / 128, 12, NB);
    qkv_fused<<<gQKV, 256, SMEM_DYN>>>(W, xT, gq, gk, gv, bq, bk, bv, q, k, vT);

    // Energy: M=c, N=d, K=t (16 chunks) -> fp32 e
    dim3 gE(NC / 128, NC / 128, NB);
    gemm_f32out<<<gE, 256, SMEM_DYN>>>(q, k,
        NT, NT, (size_t)NC * NT, (size_t)NC * NT, 16,
        e, NC, (size_t)NC * NC);

    // Softmax: 2 rows per block
    softmax_h<<<NB * NC / 2, 256>>>(e, a);

    // Output: M=c, N=t, K=d (8 chunks) -> fp32 out
    dim3 gO(NT / 128, NC / 128, NB);
    gemm_f32out<<<gO, 256, SMEM_DYN>>>(a, vT,
        NC, NC, (size_t)NC * NC, (size_t)NT * NC, 8,
        out, NT, (size_t)NC * NT);
}